// round 1
// baseline (speedup 1.0000x reference)
#include <cuda_runtime.h>
#include <mma.h>

using namespace nvcuda;

#define Bdim 8
#define Sdim 8192
#define Cdim 512
#define Hdim 128

#define NCHUNK 128            // softmax s-chunks per batch
#define CROWS  (Sdim/NCHUNK)  // 64 rows per chunk
#define KSPLIT 16             // split-K for ctx GEMM
#define SLICE  (Sdim/KSPLIT)  // 512 s-rows per split

// ---------------- scratch (static device globals; no allocations) -----------
__device__ float g_logits[(size_t)Bdim * Sdim * Hdim];                 // 33.5 MB
__device__ float g_part_m[Bdim * NCHUNK * Hdim];
__device__ float g_part_s[Bdim * NCHUNK * Hdim];
__device__ float g_stat_m[Bdim * Hdim];
__device__ float g_stat_inv[Bdim * Hdim];
__device__ float g_ctx_part[(size_t)KSPLIT * Bdim * Hdim * Cdim];      // 32 MB
__device__ float g_ctx[Bdim * Hdim * Cdim];                            // 2 MB

__device__ __forceinline__ float tf32r(float x) { return wmma::__float_to_tf32(x); }

// ============================================================================
// Kernel 1: logits = x @ W   (bias skipped: softmax over S is invariant to
// a per-h constant shift, so b cancels exactly)
// GEMM M=B*S=65536, N=128, K=512, tf32 WMMA. Block tile 64x128, K-chunk 32.
// ============================================================================
__global__ __launch_bounds__(256) void k_logits(const float* __restrict__ x,
                                                const float* __restrict__ W) {
    __shared__ float As[64][36];
    __shared__ float Bs[32][132];
    const int tid = threadIdx.x;
    const int wid = tid >> 5;
    const int wm = wid >> 1;   // 0..3 -> 16-row slice
    const int wn = wid & 1;    // 0..1 -> 64-col slice
    const int m0 = blockIdx.x * 64;

    wmma::fragment<wmma::accumulator, 16, 16, 8, float> c[4];
#pragma unroll
    for (int j = 0; j < 4; j++) wmma::fill_fragment(c[j], 0.0f);

    for (int kt = 0; kt < Cdim; kt += 32) {
#pragma unroll
        for (int i = 0; i < 2; i++) {
            int idx = tid + i * 256;           // 512 float4 of A tile
            int row = idx >> 3, col4 = idx & 7;
            float4 v = *reinterpret_cast<const float4*>(
                x + (size_t)(m0 + row) * Cdim + kt + col4 * 4);
            As[row][col4 * 4 + 0] = tf32r(v.x);
            As[row][col4 * 4 + 1] = tf32r(v.y);
            As[row][col4 * 4 + 2] = tf32r(v.z);
            As[row][col4 * 4 + 3] = tf32r(v.w);
        }
#pragma unroll
        for (int i = 0; i < 4; i++) {
            int idx = tid + i * 256;           // 1024 float4 of B tile
            int row = idx >> 5, col4 = idx & 31;
            float4 v = *reinterpret_cast<const float4*>(
                W + (size_t)(kt + row) * Hdim + col4 * 4);
            Bs[row][col4 * 4 + 0] = tf32r(v.x);
            Bs[row][col4 * 4 + 1] = tf32r(v.y);
            Bs[row][col4 * 4 + 2] = tf32r(v.z);
            Bs[row][col4 * 4 + 3] = tf32r(v.w);
        }
        __syncthreads();
#pragma unroll
        for (int kk = 0; kk < 32; kk += 8) {
            wmma::fragment<wmma::matrix_a, 16, 16, 8, wmma::precision::tf32,
                           wmma::row_major> a;
            wmma::load_matrix_sync(a, &As[wm * 16][kk], 36);
#pragma unroll
            for (int j = 0; j < 4; j++) {
                wmma::fragment<wmma::matrix_b, 16, 16, 8, wmma::precision::tf32,
                               wmma::row_major> bf;
                wmma::load_matrix_sync(bf, &Bs[kk][wn * 64 + j * 16], 132);
                wmma::mma_sync(c[j], a, bf, c[j]);
            }
        }
        __syncthreads();
    }
#pragma unroll
    for (int j = 0; j < 4; j++)
        wmma::store_matrix_sync(
            g_logits + (size_t)(m0 + wm * 16) * Hdim + wn * 64 + j * 16, c[j],
            Hdim, wmma::mem_row_major);
}

// ============================================================================
// Kernel 2: per-(b,h) online softmax stats over an s-chunk of 64 rows
// ============================================================================
__global__ __launch_bounds__(128) void k_smax_part() {
    const int b = blockIdx.y, ch = blockIdx.x;
    const int h = threadIdx.x;
    const float* p = g_logits + ((size_t)b * Sdim + (size_t)ch * CROWS) * Hdim + h;
    float m = -1e30f, s = 0.0f;
#pragma unroll 4
    for (int i = 0; i < CROWS; i++) {
        float l = p[(size_t)i * Hdim];
        float mn = fmaxf(m, l);
        s = s * __expf(m - mn) + __expf(l - mn);
        m = mn;
    }
    g_part_m[((size_t)b * NCHUNK + ch) * Hdim + h] = m;
    g_part_s[((size_t)b * NCHUNK + ch) * Hdim + h] = s;
}

// Kernel 3: combine chunk stats -> (max, 1/sum) per (b,h)
__global__ __launch_bounds__(128) void k_smax_comb() {
    const int b = blockIdx.x, h = threadIdx.x;
    float m = -1e30f, s = 0.0f;
    for (int ch = 0; ch < NCHUNK; ch++) {
        float pm = g_part_m[((size_t)b * NCHUNK + ch) * Hdim + h];
        float ps = g_part_s[((size_t)b * NCHUNK + ch) * Hdim + h];
        float mn = fmaxf(m, pm);
        s = s * __expf(m - mn) + ps * __expf(pm - mn);
        m = mn;
    }
    g_stat_m[b * Hdim + h] = m;
    g_stat_inv[b * Hdim + h] = 1.0f / s;
}

// ============================================================================
// Kernel 4: ctx_part[ks] = A[slice]^T @ x[slice] per batch.
// A computed on the fly from logits (exp(l-m)*inv). M=128(H), N=128(c-tile),
// K-slice=512 in chunks of 16. Deterministic split-K (no atomics).
// ============================================================================
__global__ __launch_bounds__(256) void k_ctx(const float* __restrict__ x) {
    __shared__ float As[16][132];  // As[s][h]  (col-major A: addr = h + s*132)
    __shared__ float Bs[16][132];  // Bs[s][c]
    __shared__ float sm[Hdim], sinv[Hdim];
    const int tid = threadIdx.x, wid = tid >> 5;
    const int wm = wid >> 1;   // 0..3 -> 32 h-rows
    const int wn = wid & 1;    // 0..1 -> 64 c-cols
    const int ct = blockIdx.x; // c tile (0..3)
    const int ks = blockIdx.y; // k split (0..15)
    const int b = blockIdx.z;

    if (tid < Hdim) {
        sm[tid] = g_stat_m[b * Hdim + tid];
        sinv[tid] = g_stat_inv[b * Hdim + tid];
    }
    __syncthreads();

    wmma::fragment<wmma::accumulator, 16, 16, 8, float> c[2][4];
#pragma unroll
    for (int i = 0; i < 2; i++)
#pragma unroll
        for (int j = 0; j < 4; j++) wmma::fill_fragment(c[i][j], 0.0f);

    for (int kc = 0; kc < SLICE / 16; kc++) {
        const int sb = ks * SLICE + kc * 16;
#pragma unroll
        for (int i = 0; i < 2; i++) {
            int idx = tid + i * 256;  // 512 float4 per tile
            int row = idx >> 5, col4 = idx & 31;
            int h0 = col4 * 4;
            float4 v = *reinterpret_cast<const float4*>(
                g_logits + ((size_t)b * Sdim + sb + row) * Hdim + h0);
            As[row][h0 + 0] = tf32r(__expf(v.x - sm[h0 + 0]) * sinv[h0 + 0]);
            As[row][h0 + 1] = tf32r(__expf(v.y - sm[h0 + 1]) * sinv[h0 + 1]);
            As[row][h0 + 2] = tf32r(__expf(v.z - sm[h0 + 2]) * sinv[h0 + 2]);
            As[row][h0 + 3] = tf32r(__expf(v.w - sm[h0 + 3]) * sinv[h0 + 3]);
            float4 u = *reinterpret_cast<const float4*>(
                x + ((size_t)b * Sdim + sb + row) * Cdim + ct * 128 + h0);
            Bs[row][h0 + 0] = tf32r(u.x);
            Bs[row][h0 + 1] = tf32r(u.y);
            Bs[row][h0 + 2] = tf32r(u.z);
            Bs[row][h0 + 3] = tf32r(u.w);
        }
        __syncthreads();
#pragma unroll
        for (int kk = 0; kk < 16; kk += 8) {
            wmma::fragment<wmma::matrix_a, 16, 16, 8, wmma::precision::tf32,
                           wmma::col_major> a[2];
#pragma unroll
            for (int i = 0; i < 2; i++)
                wmma::load_matrix_sync(a[i], &As[kk][wm * 32 + i * 16], 132);
#pragma unroll
            for (int j = 0; j < 4; j++) {
                wmma::fragment<wmma::matrix_b, 16, 16, 8, wmma::precision::tf32,
                               wmma::row_major> bf;
                wmma::load_matrix_sync(bf, &Bs[kk][wn * 64 + j * 16], 132);
#pragma unroll
                for (int i = 0; i < 2; i++) wmma::mma_sync(c[i][j], a[i], bf, c[i][j]);
            }
        }
        __syncthreads();
    }
#pragma unroll
    for (int i = 0; i < 2; i++)
#pragma unroll
        for (int j = 0; j < 4; j++)
            wmma::store_matrix_sync(
                g_ctx_part + (((size_t)ks * Bdim + b) * Hdim + wm * 32 + i * 16) * Cdim +
                    ct * 128 + wn * 64 + j * 16,
                c[i][j], Cdim, wmma::mem_row_major);
}

// Kernel 5: deterministic reduction of split-K partials
__global__ __launch_bounds__(256) void k_ctx_reduce() {
    const size_t idx = (size_t)blockIdx.x * 256 + threadIdx.x;  // B*H*C = 524288
    float s = 0.0f;
#pragma unroll
    for (int ks = 0; ks < KSPLIT; ks++)
        s += g_ctx_part[(size_t)ks * Bdim * Hdim * Cdim + idx];
    g_ctx[idx] = s;
}

// ============================================================================
// Kernel 6: out = A @ ctx per batch. M=8192, N=512 (tiles of 128), K=128
// (chunks of 32). A recomputed from logits on the fly.
// ============================================================================
__global__ __launch_bounds__(256) void k_out(float* __restrict__ out) {
    __shared__ float As[64][36];
    __shared__ float Bs[32][132];
    __shared__ float sm[Hdim], sinv[Hdim];
    const int tid = threadIdx.x, wid = tid >> 5;
    const int wm = wid >> 1, wn = wid & 1;
    const int mt = blockIdx.x, ct = blockIdx.y, b = blockIdx.z;
    const int m0 = mt * 64, c0 = ct * 128;

    if (tid < Hdim) {
        sm[tid] = g_stat_m[b * Hdim + tid];
        sinv[tid] = g_stat_inv[b * Hdim + tid];
    }
    __syncthreads();

    wmma::fragment<wmma::accumulator, 16, 16, 8, float> c[4];
#pragma unroll
    for (int j = 0; j < 4; j++) wmma::fill_fragment(c[j], 0.0f);

    for (int kt = 0; kt < Hdim; kt += 32) {
#pragma unroll
        for (int i = 0; i < 2; i++) {
            int idx = tid + i * 256;
            int row = idx >> 3, col4 = idx & 7;
            int h = kt + col4 * 4;
            float4 v = *reinterpret_cast<const float4*>(
                g_logits + ((size_t)b * Sdim + m0 + row) * Hdim + h);
            As[row][col4 * 4 + 0] = tf32r(__expf(v.x - sm[h + 0]) * sinv[h + 0]);
            As[row][col4 * 4 + 1] = tf32r(__expf(v.y - sm[h + 1]) * sinv[h + 1]);
            As[row][col4 * 4 + 2] = tf32r(__expf(v.z - sm[h + 2]) * sinv[h + 2]);
            As[row][col4 * 4 + 3] = tf32r(__expf(v.w - sm[h + 3]) * sinv[h + 3]);
        }
#pragma unroll
        for (int i = 0; i < 4; i++) {
            int idx = tid + i * 256;
            int row = idx >> 5, col4 = idx & 31;
            float4 v = *reinterpret_cast<const float4*>(
                g_ctx + ((size_t)b * Hdim + kt + row) * Cdim + c0 + col4 * 4);
            Bs[row][col4 * 4 + 0] = tf32r(v.x);
            Bs[row][col4 * 4 + 1] = tf32r(v.y);
            Bs[row][col4 * 4 + 2] = tf32r(v.z);
            Bs[row][col4 * 4 + 3] = tf32r(v.w);
        }
        __syncthreads();
#pragma unroll
        for (int kk = 0; kk < 32; kk += 8) {
            wmma::fragment<wmma::matrix_a, 16, 16, 8, wmma::precision::tf32,
                           wmma::row_major> a;
            wmma::load_matrix_sync(a, &As[wm * 16][kk], 36);
#pragma unroll
            for (int j = 0; j < 4; j++) {
                wmma::fragment<wmma::matrix_b, 16, 16, 8, wmma::precision::tf32,
                               wmma::row_major> bf;
                wmma::load_matrix_sync(bf, &Bs[kk][wn * 64 + j * 16], 132);
                wmma::mma_sync(c[j], a, bf, c[j]);
            }
        }
        __syncthreads();
    }
#pragma unroll
    for (int j = 0; j < 4; j++)
        wmma::store_matrix_sync(
            out + ((size_t)b * Sdim + m0 + wm * 16) * Cdim + c0 + wn * 64 + j * 16,
            c[j], Cdim, wmma::mem_row_major);
}

// ============================================================================
extern "C" void kernel_launch(void* const* d_in, const int* in_sizes, int n_in,
                              void* d_out, int out_size) {
    const float* x = (const float*)d_in[0];  // [B, S, C]
    const float* W = (const float*)d_in[1];  // [C, H]
    // d_in[2] = bias [H]; mathematically irrelevant: softmax over S cancels a
    // per-h constant shift, so it never affects the output.
    float* out = (float*)d_out;              // [B, S, C]

    k_logits<<<(Bdim * Sdim) / 64, 256>>>(x, W);
    k_smax_part<<<dim3(NCHUNK, Bdim), 128>>>();
    k_smax_comb<<<Bdim, 128>>>();
    k_ctx<<<dim3(Cdim / 128, KSPLIT, Bdim), 256>>>(x);
    k_ctx_reduce<<<(Bdim * Hdim * Cdim) / 256, 256>>>();
    k_out<<<dim3(Sdim / 64, Cdim / 128, Bdim), 256>>>(out);
}

// round 2
// speedup vs baseline: 1.0339x; 1.0339x over previous
#include <cuda_runtime.h>
#include <mma.h>

using namespace nvcuda;

#define Bdim 8
#define Sdim 8192
#define Cdim 512
#define Hdim 128

#define KSPLIT 8
#define SLICE  (Sdim/KSPLIT)   // 1024
#define NCH    64              // logits tiles (128 rows) per batch

// ---------------- scratch (static device globals) ---------------------------
__device__ float g_logits[(size_t)Bdim * Sdim * Hdim];                 // 33.5 MB (becomes A)
__device__ float g_part_m[Bdim * NCH * Hdim];
__device__ float g_part_s[Bdim * NCH * Hdim];
__device__ float g_stat_m[Bdim * Hdim];
__device__ float g_stat_inv[Bdim * Hdim];
__device__ float g_ctx_part[(size_t)KSPLIT * Bdim * Hdim * Cdim];      // 16.8 MB
__device__ float g_ctx[Bdim * Hdim * Cdim];                            // 2 MB

__device__ __forceinline__ float tf32r(float x) { return wmma::__float_to_tf32(x); }

__device__ __forceinline__ void cp16(float* smem_dst, const float* gmem_src) {
    unsigned s = (unsigned)__cvta_generic_to_shared(smem_dst);
    asm volatile("cp.async.cg.shared.global [%0], [%1], 16;\n" ::"r"(s), "l"(gmem_src));
}
#define CP_COMMIT asm volatile("cp.async.commit_group;\n")
#define CP_WAIT1  asm volatile("cp.async.wait_group 1;\n")
#define CP_WAIT0  asm volatile("cp.async.wait_group 0;\n")

// ============================================================================
// K1: logits = x @ W (bias skipped — softmax over S cancels per-h constants)
// + fused per-128-row-tile column softmax stats.
// M=65536, N=128, K=512. Block 128x128, KC=32, cp.async double buffer.
// ============================================================================
__global__ __launch_bounds__(256) void k_logits(const float* __restrict__ x,
                                                const float* __restrict__ W) {
    extern __shared__ float sh[];
    float* As = sh;               // [2][128][36]
    float* Bs = sh + 2 * 128 * 36; // [2][32][132]
    float* pm = sh + 17664;        // [256]
    float* ps = sh + 17920;        // [256]
    const int tid = threadIdx.x, wid = tid >> 5;
    const int wm = wid >> 1, wn = wid & 1;
    const int m0 = blockIdx.x * 128;

    wmma::fragment<wmma::accumulator, 16, 16, 8, float> c[2][4];
#pragma unroll
    for (int i = 0; i < 2; i++)
#pragma unroll
        for (int j = 0; j < 4; j++) wmma::fill_fragment(c[i][j], 0.0f);

    auto load_tiles = [&](int buf, int kt) {
#pragma unroll
        for (int i = 0; i < 4; i++) {   // A: 128x32 = 1024 f4
            int idx = tid + i * 256;
            int row = idx >> 3, c4 = idx & 7;
            cp16(As + buf * 4608 + row * 36 + c4 * 4,
                 x + (size_t)(m0 + row) * Cdim + kt + c4 * 4);
        }
#pragma unroll
        for (int i = 0; i < 4; i++) {   // B: 32x128 = 1024 f4
            int idx = tid + i * 256;
            int row = idx >> 5, c4 = idx & 31;
            cp16(Bs + buf * 4224 + row * 132 + c4 * 4,
                 W + (size_t)(kt + row) * Hdim + c4 * 4);
        }
    };

    load_tiles(0, 0);
    CP_COMMIT;
    int buf = 0;
    for (int it = 0; it < 16; ++it) {
        if (it < 15) { load_tiles(buf ^ 1, (it + 1) * 32); CP_COMMIT; CP_WAIT1; }
        else CP_WAIT0;
        __syncthreads();
#pragma unroll
        for (int kk = 0; kk < 32; kk += 8) {
            wmma::fragment<wmma::matrix_a, 16, 16, 8, wmma::precision::tf32,
                           wmma::row_major> a[2];
#pragma unroll
            for (int i = 0; i < 2; i++) {
                wmma::load_matrix_sync(a[i],
                    As + buf * 4608 + (wm * 32 + i * 16) * 36 + kk, 36);
#pragma unroll
                for (int t = 0; t < a[i].num_elements; t++)
                    a[i].x[t] = tf32r(a[i].x[t]);
            }
#pragma unroll
            for (int j = 0; j < 4; j++) {
                wmma::fragment<wmma::matrix_b, 16, 16, 8, wmma::precision::tf32,
                               wmma::row_major> bf;
                wmma::load_matrix_sync(bf,
                    Bs + buf * 4224 + kk * 132 + wn * 64 + j * 16, 132);
#pragma unroll
                for (int t = 0; t < bf.num_elements; t++)
                    bf.x[t] = tf32r(bf.x[t]);
#pragma unroll
                for (int i = 0; i < 2; i++) wmma::mma_sync(c[i][j], a[i], bf, c[i][j]);
            }
        }
        __syncthreads();
        buf ^= 1;
    }

    // epilogue: tile -> smem (stride 132), then gmem write + column stats
#pragma unroll
    for (int i = 0; i < 2; i++)
#pragma unroll
        for (int j = 0; j < 4; j++)
            wmma::store_matrix_sync(
                sh + (wm * 32 + i * 16) * 132 + wn * 64 + j * 16, c[i][j], 132,
                wmma::mem_row_major);
    __syncthreads();
#pragma unroll
    for (int i = 0; i < 16; i++) {
        int idx = tid + i * 256;
        int row = idx >> 5, c4 = idx & 31;
        float4 v = *reinterpret_cast<float4*>(sh + row * 132 + c4 * 4);
        *reinterpret_cast<float4*>(g_logits + (size_t)(m0 + row) * Hdim + c4 * 4) = v;
    }
    // stats: 2 threads per column, 64 rows each
    {
        const int col = tid & 127, half = tid >> 7;
        float m = -1e30f;
#pragma unroll 8
        for (int r = half * 64; r < half * 64 + 64; r++)
            m = fmaxf(m, sh[r * 132 + col]);
        float s = 0.0f;
#pragma unroll 8
        for (int r = half * 64; r < half * 64 + 64; r++)
            s += __expf(sh[r * 132 + col] - m);
        pm[tid] = m; ps[tid] = s;
        __syncthreads();
        if (half == 0) {
            float m1 = pm[col + 128], s1 = ps[col + 128];
            float mn = fmaxf(m, m1);
            float sc = s * __expf(m - mn) + s1 * __expf(m1 - mn);
            const int b = blockIdx.x >> 6, ch = blockIdx.x & 63;
            g_part_m[((size_t)b * NCH + ch) * Hdim + col] = mn;
            g_part_s[((size_t)b * NCH + ch) * Hdim + col] = sc;
        }
    }
}

// K2: combine chunk stats
__global__ __launch_bounds__(128) void k_comb() {
    const int b = blockIdx.x, h = threadIdx.x;
    float m = -1e30f, s = 0.0f;
    for (int ch = 0; ch < NCH; ch++) {
        float pmv = g_part_m[((size_t)b * NCH + ch) * Hdim + h];
        float psv = g_part_s[((size_t)b * NCH + ch) * Hdim + h];
        float mn = fmaxf(m, pmv);
        s = s * __expf(m - mn) + psv * __expf(pmv - mn);
        m = mn;
    }
    g_stat_m[b * Hdim + h] = m;
    g_stat_inv[b * Hdim + h] = 1.0f / s;
}

// K3: A = tf32(exp(l - m) * inv), in place over g_logits
__global__ __launch_bounds__(256) void k_aconv() {
    const size_t f4 = (size_t)blockIdx.x * 256 + threadIdx.x;  // 2,097,152 total
    const size_t e0 = f4 * 4;
    const int b = (int)(e0 >> 20);          // 8192*128 = 2^20 per batch
    const int h0 = (int)(e0 & 127);
    float4 l = reinterpret_cast<float4*>(g_logits)[f4];
    const float* sm = g_stat_m + b * Hdim + h0;
    const float* si = g_stat_inv + b * Hdim + h0;
    l.x = tf32r(__expf(l.x - __ldg(sm + 0)) * __ldg(si + 0));
    l.y = tf32r(__expf(l.y - __ldg(sm + 1)) * __ldg(si + 1));
    l.z = tf32r(__expf(l.z - __ldg(sm + 2)) * __ldg(si + 2));
    l.w = tf32r(__expf(l.w - __ldg(sm + 3)) * __ldg(si + 3));
    reinterpret_cast<float4*>(g_logits)[f4] = l;
}

// ============================================================================
// K4: ctx_part[ks] = A[slice]^T @ x[slice]. M=128(H), N=128(c-tile), K=1024.
// KC=32, cp.async double buffer. grid (4, 8, 8) = 256 blocks = 1 wave.
// ============================================================================
__global__ __launch_bounds__(256) void k_ctx(const float* __restrict__ x) {
    extern __shared__ float sh[];
    float* As = sh;          // [2][32][132]  (A rows: s, cols: h)
    float* Bs = sh + 8448;   // [2][32][132]  (x rows: s, cols: c)
    const int tid = threadIdx.x, wid = tid >> 5;
    const int wm = wid >> 1, wn = wid & 1;
    const int ct = blockIdx.x, ks = blockIdx.y, b = blockIdx.z;
    const int sbase = ks * SLICE;

    wmma::fragment<wmma::accumulator, 16, 16, 8, float> c[2][4];
#pragma unroll
    for (int i = 0; i < 2; i++)
#pragma unroll
        for (int j = 0; j < 4; j++) wmma::fill_fragment(c[i][j], 0.0f);

    auto load_tiles = [&](int buf, int s0) {
#pragma unroll
        for (int i = 0; i < 4; i++) {
            int idx = tid + i * 256;
            int row = idx >> 5, c4 = idx & 31;
            cp16(As + buf * 4224 + row * 132 + c4 * 4,
                 g_logits + ((size_t)b * Sdim + s0 + row) * Hdim + c4 * 4);
        }
#pragma unroll
        for (int i = 0; i < 4; i++) {
            int idx = tid + i * 256;
            int row = idx >> 5, c4 = idx & 31;
            cp16(Bs + buf * 4224 + row * 132 + c4 * 4,
                 x + ((size_t)b * Sdim + s0 + row) * Cdim + ct * 128 + c4 * 4);
        }
    };

    load_tiles(0, sbase);
    CP_COMMIT;
    int buf = 0;
    for (int it = 0; it < SLICE / 32; ++it) {
        if (it < SLICE / 32 - 1) {
            load_tiles(buf ^ 1, sbase + (it + 1) * 32); CP_COMMIT; CP_WAIT1;
        } else CP_WAIT0;
        __syncthreads();
#pragma unroll
        for (int kk = 0; kk < 32; kk += 8) {
            wmma::fragment<wmma::matrix_a, 16, 16, 8, wmma::precision::tf32,
                           wmma::col_major> a[2];
#pragma unroll
            for (int i = 0; i < 2; i++)
                wmma::load_matrix_sync(a[i],
                    As + buf * 4224 + kk * 132 + wm * 32 + i * 16, 132);
#pragma unroll
            for (int j = 0; j < 4; j++) {
                wmma::fragment<wmma::matrix_b, 16, 16, 8, wmma::precision::tf32,
                               wmma::row_major> bf;
                wmma::load_matrix_sync(bf,
                    Bs + buf * 4224 + kk * 132 + wn * 64 + j * 16, 132);
#pragma unroll
                for (int i = 0; i < 2; i++) wmma::mma_sync(c[i][j], a[i], bf, c[i][j]);
            }
        }
        __syncthreads();
        buf ^= 1;
    }
#pragma unroll
    for (int i = 0; i < 2; i++)
#pragma unroll
        for (int j = 0; j < 4; j++)
            wmma::store_matrix_sync(
                g_ctx_part + (((size_t)ks * Bdim + b) * Hdim + wm * 32 + i * 16) * Cdim +
                    ct * 128 + wn * 64 + j * 16,
                c[i][j], Cdim, wmma::mem_row_major);
}

// K5: deterministic split-K reduce (float4)
__global__ __launch_bounds__(256) void k_reduce() {
    const size_t f4 = (size_t)blockIdx.x * 256 + threadIdx.x;  // 131072 total
    float4 s = make_float4(0.f, 0.f, 0.f, 0.f);
#pragma unroll
    for (int p = 0; p < KSPLIT; p++) {
        float4 v = reinterpret_cast<float4*>(
            g_ctx_part + (size_t)p * Bdim * Hdim * Cdim)[f4];
        s.x += v.x; s.y += v.y; s.z += v.z; s.w += v.w;
    }
    reinterpret_cast<float4*>(g_ctx)[f4] = s;
}

// ============================================================================
// K6: out = A @ ctx. M=8192, N=512, K=128 per batch. Block 128x128, KC=32.
// ============================================================================
__global__ __launch_bounds__(256) void k_out(float* __restrict__ out) {
    extern __shared__ float sh[];
    float* As = sh;          // [2][128][36]
    float* Bs = sh + 9216;   // [2][32][132]
    const int tid = threadIdx.x, wid = tid >> 5;
    const int wm = wid >> 1, wn = wid & 1;
    const int mt = blockIdx.x, ct = blockIdx.y, b = blockIdx.z;
    const int m0 = mt * 128;

    wmma::fragment<wmma::accumulator, 16, 16, 8, float> c[2][4];
#pragma unroll
    for (int i = 0; i < 2; i++)
#pragma unroll
        for (int j = 0; j < 4; j++) wmma::fill_fragment(c[i][j], 0.0f);

    auto load_tiles = [&](int buf, int kt) {
#pragma unroll
        for (int i = 0; i < 4; i++) {   // A: 128 x 32
            int idx = tid + i * 256;
            int row = idx >> 3, c4 = idx & 7;
            cp16(As + buf * 4608 + row * 36 + c4 * 4,
                 g_logits + ((size_t)b * Sdim + m0 + row) * Hdim + kt + c4 * 4);
        }
#pragma unroll
        for (int i = 0; i < 4; i++) {   // B: 32 x 128
            int idx = tid + i * 256;
            int row = idx >> 5, c4 = idx & 31;
            cp16(Bs + buf * 4224 + row * 132 + c4 * 4,
                 g_ctx + ((size_t)b * Hdim + kt + row) * Cdim + ct * 128 + c4 * 4);
        }
    };

    load_tiles(0, 0);
    CP_COMMIT;
    int buf = 0;
    for (int it = 0; it < 4; ++it) {
        if (it < 3) { load_tiles(buf ^ 1, (it + 1) * 32); CP_COMMIT; CP_WAIT1; }
        else CP_WAIT0;
        __syncthreads();
#pragma unroll
        for (int kk = 0; kk < 32; kk += 8) {
            wmma::fragment<wmma::matrix_a, 16, 16, 8, wmma::precision::tf32,
                           wmma::row_major> a[2];
#pragma unroll
            for (int i = 0; i < 2; i++)
                wmma::load_matrix_sync(a[i],
                    As + buf * 4608 + (wm * 32 + i * 16) * 36 + kk, 36);
#pragma unroll
            for (int j = 0; j < 4; j++) {
                wmma::fragment<wmma::matrix_b, 16, 16, 8, wmma::precision::tf32,
                               wmma::row_major> bf;
                wmma::load_matrix_sync(bf,
                    Bs + buf * 4224 + kk * 132 + wn * 64 + j * 16, 132);
#pragma unroll
                for (int i = 0; i < 2; i++) wmma::mma_sync(c[i][j], a[i], bf, c[i][j]);
            }
        }
        __syncthreads();
        buf ^= 1;
    }
#pragma unroll
    for (int i = 0; i < 2; i++)
#pragma unroll
        for (int j = 0; j < 4; j++)
            wmma::store_matrix_sync(
                out + ((size_t)b * Sdim + m0 + wm * 32 + i * 16) * Cdim + ct * 128 +
                    wn * 64 + j * 16,
                c[i][j], Cdim, wmma::mem_row_major);
}

// ============================================================================
extern "C" void kernel_launch(void* const* d_in, const int* in_sizes, int n_in,
                              void* d_out, int out_size) {
    const float* x = (const float*)d_in[0];  // [B, S, C]
    const float* W = (const float*)d_in[1];  // [C, H]
    // d_in[2] (bias) cancels in softmax over S — skipped, exact.
    float* out = (float*)d_out;

    const size_t sh_logits = 18176 * 4;  // As/Bs + stats scratch
    const size_t sh_ctx    = 16896 * 4;
    const size_t sh_out    = 17664 * 4;
    cudaFuncSetAttribute(k_logits, cudaFuncAttributeMaxDynamicSharedMemorySize,
                         (int)sh_logits);
    cudaFuncSetAttribute(k_ctx, cudaFuncAttributeMaxDynamicSharedMemorySize,
                         (int)sh_ctx);
    cudaFuncSetAttribute(k_out, cudaFuncAttributeMaxDynamicSharedMemorySize,
                         (int)sh_out);

    k_logits<<<(Bdim * Sdim) / 128, 256, sh_logits>>>(x, W);
    k_comb<<<Bdim, 128>>>();
    k_aconv<<<8192, 256>>>();
    k_ctx<<<dim3(Cdim / 128, KSPLIT, Bdim), 256, sh_ctx>>>(x);
    k_reduce<<<512, 256>>>();
    k_out<<<dim3(Sdim / 128, Cdim / 128, Bdim), 256, sh_out>>>(out);
}

// round 3
// speedup vs baseline: 1.1623x; 1.1242x over previous
#include <cuda_runtime.h>
#include <mma.h>

using namespace nvcuda;

#define Bdim 8
#define Sdim 8192
#define Cdim 512
#define Hdim 128

#define KSPLIT 16
#define SLICE  (Sdim/KSPLIT)   // 512
#define NCH    64              // logits tiles (128 rows) per batch

// ---------------- scratch (static device globals) ---------------------------
__device__ float g_logits[(size_t)Bdim * Sdim * Hdim];                 // 33.5 MB (becomes A)
__device__ float g_part_m[Bdim * NCH * Hdim];
__device__ float g_part_s[Bdim * NCH * Hdim];
__device__ float g_stat_m[Bdim * Hdim];
__device__ float g_stat_inv[Bdim * Hdim];
__device__ float g_ctx_part[(size_t)KSPLIT * Bdim * Hdim * Cdim];      // 33.5 MB
__device__ float g_ctx[Bdim * Hdim * Cdim];                            // 2 MB

__device__ __forceinline__ float tf32r(float x) { return wmma::__float_to_tf32(x); }

__device__ __forceinline__ void cp16(float* smem_dst, const float* gmem_src) {
    unsigned s = (unsigned)__cvta_generic_to_shared(smem_dst);
    asm volatile("cp.async.cg.shared.global [%0], [%1], 16;\n" ::"r"(s), "l"(gmem_src));
}
#define CP_COMMIT asm volatile("cp.async.commit_group;\n")
#define CP_WAIT2  asm volatile("cp.async.wait_group 2;\n")

// ============================================================================
// K1: logits = x @ W (bias skipped — softmax over S cancels per-h constants)
// + fused per-128-row-tile column softmax stats.
// M=65536, N=128, K=512. Block 128x128, KC=32, 3-stage cp.async pipeline.
// ============================================================================
__global__ __launch_bounds__(256, 2) void k_logits(const float* __restrict__ x,
                                                   const float* __restrict__ W) {
    extern __shared__ float sh[];
    // 3 stages of (A 128x36 + B 32x132) = 3*8832 floats
    const int tid = threadIdx.x, wid = tid >> 5;
    const int wm = wid >> 1, wn = wid & 1;
    const int m0 = blockIdx.x * 128;

    wmma::fragment<wmma::accumulator, 16, 16, 8, float> c[2][4];
#pragma unroll
    for (int i = 0; i < 2; i++)
#pragma unroll
        for (int j = 0; j < 4; j++) wmma::fill_fragment(c[i][j], 0.0f);

    auto As = [&](int st) { return sh + st * 8832; };
    auto Bs = [&](int st) { return sh + st * 8832 + 4608; };

    auto load_tiles = [&](int st, int it) {
        const int kt = it * 32;
        float* a = As(st);
        float* bsh = Bs(st);
#pragma unroll
        for (int i = 0; i < 4; i++) {   // A: 128x32 = 1024 f4
            int idx = tid + i * 256;
            int row = idx >> 3, c4 = idx & 7;
            cp16(a + row * 36 + c4 * 4,
                 x + (size_t)(m0 + row) * Cdim + kt + c4 * 4);
        }
#pragma unroll
        for (int i = 0; i < 4; i++) {   // B: 32x128 = 1024 f4
            int idx = tid + i * 256;
            int row = idx >> 5, c4 = idx & 31;
            cp16(bsh + row * 132 + c4 * 4,
                 W + (size_t)(kt + row) * Hdim + c4 * 4);
        }
    };

    const int NIT = 16;
    load_tiles(0, 0); CP_COMMIT;
    load_tiles(1, 1); CP_COMMIT;
    for (int it = 0; it < NIT; ++it) {
        if (it + 2 < NIT) load_tiles((it + 2) % 3, it + 2);
        CP_COMMIT;          // empty groups at tail keep the count consistent
        CP_WAIT2;
        __syncthreads();
        const int st = it % 3;
#pragma unroll
        for (int kk = 0; kk < 32; kk += 8) {
            wmma::fragment<wmma::matrix_a, 16, 16, 8, wmma::precision::tf32,
                           wmma::row_major> a[2];
#pragma unroll
            for (int i = 0; i < 2; i++) {
                wmma::load_matrix_sync(a[i], As(st) + (wm * 32 + i * 16) * 36 + kk, 36);
#pragma unroll
                for (int t = 0; t < a[i].num_elements; t++) a[i].x[t] = tf32r(a[i].x[t]);
            }
#pragma unroll
            for (int j = 0; j < 4; j++) {
                wmma::fragment<wmma::matrix_b, 16, 16, 8, wmma::precision::tf32,
                               wmma::row_major> bf;
                wmma::load_matrix_sync(bf, Bs(st) + kk * 132 + wn * 64 + j * 16, 132);
#pragma unroll
                for (int t = 0; t < bf.num_elements; t++) bf.x[t] = tf32r(bf.x[t]);
#pragma unroll
                for (int i = 0; i < 2; i++) wmma::mma_sync(c[i][j], a[i], bf, c[i][j]);
            }
        }
        __syncthreads();
    }

    // epilogue: tile -> smem (stride 132), then gmem write + column stats
#pragma unroll
    for (int i = 0; i < 2; i++)
#pragma unroll
        for (int j = 0; j < 4; j++)
            wmma::store_matrix_sync(
                sh + (wm * 32 + i * 16) * 132 + wn * 64 + j * 16, c[i][j], 132,
                wmma::mem_row_major);
    __syncthreads();
#pragma unroll
    for (int i = 0; i < 16; i++) {
        int idx = tid + i * 256;
        int row = idx >> 5, c4 = idx & 31;
        float4 v = *reinterpret_cast<float4*>(sh + row * 132 + c4 * 4);
        *reinterpret_cast<float4*>(g_logits + (size_t)(m0 + row) * Hdim + c4 * 4) = v;
    }
    {
        float* pm = sh + 16896;
        float* ps = sh + 17152;
        const int col = tid & 127, half = tid >> 7;
        float m = -1e30f;
#pragma unroll 8
        for (int r = half * 64; r < half * 64 + 64; r++)
            m = fmaxf(m, sh[r * 132 + col]);
        float s = 0.0f;
#pragma unroll 8
        for (int r = half * 64; r < half * 64 + 64; r++)
            s += __expf(sh[r * 132 + col] - m);
        pm[tid] = m; ps[tid] = s;
        __syncthreads();
        if (half == 0) {
            float m1 = pm[col + 128], s1 = ps[col + 128];
            float mn = fmaxf(m, m1);
            float sc = s * __expf(m - mn) + s1 * __expf(m1 - mn);
            const int b = blockIdx.x >> 6, ch = blockIdx.x & 63;
            g_part_m[((size_t)b * NCH + ch) * Hdim + col] = mn;
            g_part_s[((size_t)b * NCH + ch) * Hdim + col] = sc;
        }
    }
}

// K2: combine chunk stats
__global__ __launch_bounds__(128) void k_comb() {
    const int b = blockIdx.x, h = threadIdx.x;
    float m = -1e30f, s = 0.0f;
    for (int ch = 0; ch < NCH; ch++) {
        float pmv = g_part_m[((size_t)b * NCH + ch) * Hdim + h];
        float psv = g_part_s[((size_t)b * NCH + ch) * Hdim + h];
        float mn = fmaxf(m, pmv);
        s = s * __expf(m - mn) + psv * __expf(pmv - mn);
        m = mn;
    }
    g_stat_m[b * Hdim + h] = m;
    g_stat_inv[b * Hdim + h] = 1.0f / s;
}

// K3: A = tf32_RN(exp(l - m) * inv), in place over g_logits
__global__ __launch_bounds__(256) void k_aconv() {
    const size_t f4 = (size_t)blockIdx.x * 256 + threadIdx.x;  // 2,097,152 total
    const size_t e0 = f4 * 4;
    const int b = (int)(e0 >> 20);
    const int h0 = (int)(e0 & 127);
    float4 l = reinterpret_cast<float4*>(g_logits)[f4];
    const float* sm = g_stat_m + b * Hdim + h0;
    const float* si = g_stat_inv + b * Hdim + h0;
    l.x = tf32r(__expf(l.x - __ldg(sm + 0)) * __ldg(si + 0));
    l.y = tf32r(__expf(l.y - __ldg(sm + 1)) * __ldg(si + 1));
    l.z = tf32r(__expf(l.z - __ldg(sm + 2)) * __ldg(si + 2));
    l.w = tf32r(__expf(l.w - __ldg(sm + 3)) * __ldg(si + 3));
    reinterpret_cast<float4*>(g_logits)[f4] = l;
}

// ============================================================================
// K4: ctx_part[ks] = A[slice]^T @ x[slice]. M=128(H), N=128(c-tile), K=512.
// KC=32, 3-stage pipeline. grid (4, 16, 8) = 512 blocks, ct fastest -> L2
// dedups the 4x re-read of each A slice.
// ============================================================================
__global__ __launch_bounds__(256, 2) void k_ctx(const float* __restrict__ x) {
    extern __shared__ float sh[];
    // 3 stages of (A 32x132 + B 32x132) = 3*8448 floats
    const int tid = threadIdx.x, wid = tid >> 5;
    const int wm = wid >> 1, wn = wid & 1;
    const int ct = blockIdx.x, ks = blockIdx.y, b = blockIdx.z;
    const int sbase = ks * SLICE;

    wmma::fragment<wmma::accumulator, 16, 16, 8, float> c[2][4];
#pragma unroll
    for (int i = 0; i < 2; i++)
#pragma unroll
        for (int j = 0; j < 4; j++) wmma::fill_fragment(c[i][j], 0.0f);

    auto As = [&](int st) { return sh + st * 8448; };
    auto Bs = [&](int st) { return sh + st * 8448 + 4224; };

    auto load_tiles = [&](int st, int it) {
        const int s0 = sbase + it * 32;
        float* a = As(st);
        float* bsh = Bs(st);
#pragma unroll
        for (int i = 0; i < 4; i++) {
            int idx = tid + i * 256;
            int row = idx >> 5, c4 = idx & 31;
            cp16(a + row * 132 + c4 * 4,
                 g_logits + ((size_t)b * Sdim + s0 + row) * Hdim + c4 * 4);
        }
#pragma unroll
        for (int i = 0; i < 4; i++) {
            int idx = tid + i * 256;
            int row = idx >> 5, c4 = idx & 31;
            cp16(bsh + row * 132 + c4 * 4,
                 x + ((size_t)b * Sdim + s0 + row) * Cdim + ct * 128 + c4 * 4);
        }
    };

    const int NIT = SLICE / 32;  // 16
    load_tiles(0, 0); CP_COMMIT;
    load_tiles(1, 1); CP_COMMIT;
    for (int it = 0; it < NIT; ++it) {
        if (it + 2 < NIT) load_tiles((it + 2) % 3, it + 2);
        CP_COMMIT;
        CP_WAIT2;
        __syncthreads();
        const int st = it % 3;
#pragma unroll
        for (int kk = 0; kk < 32; kk += 8) {
            wmma::fragment<wmma::matrix_a, 16, 16, 8, wmma::precision::tf32,
                           wmma::col_major> a[2];
#pragma unroll
            for (int i = 0; i < 2; i++)
                wmma::load_matrix_sync(a[i], As(st) + kk * 132 + wm * 32 + i * 16, 132);
#pragma unroll
            for (int j = 0; j < 4; j++) {
                wmma::fragment<wmma::matrix_b, 16, 16, 8, wmma::precision::tf32,
                               wmma::row_major> bf;
                wmma::load_matrix_sync(bf, Bs(st) + kk * 132 + wn * 64 + j * 16, 132);
#pragma unroll
                for (int t = 0; t < bf.num_elements; t++) bf.x[t] = tf32r(bf.x[t]);
#pragma unroll
                for (int i = 0; i < 2; i++) wmma::mma_sync(c[i][j], a[i], bf, c[i][j]);
            }
        }
        __syncthreads();
    }
#pragma unroll
    for (int i = 0; i < 2; i++)
#pragma unroll
        for (int j = 0; j < 4; j++)
            wmma::store_matrix_sync(
                g_ctx_part + (((size_t)ks * Bdim + b) * Hdim + wm * 32 + i * 16) * Cdim +
                    ct * 128 + wn * 64 + j * 16,
                c[i][j], Cdim, wmma::mem_row_major);
}

// K5: deterministic split-K reduce (float4), output RN-rounded to tf32 so
// k_out consumes pre-rounded operands.
__global__ __launch_bounds__(256) void k_reduce() {
    const size_t f4 = (size_t)blockIdx.x * 256 + threadIdx.x;  // 131072 total
    float4 s = make_float4(0.f, 0.f, 0.f, 0.f);
#pragma unroll
    for (int p = 0; p < KSPLIT; p++) {
        float4 v = reinterpret_cast<float4*>(
            g_ctx_part + (size_t)p * Bdim * Hdim * Cdim)[f4];
        s.x += v.x; s.y += v.y; s.z += v.z; s.w += v.w;
    }
    s.x = tf32r(s.x); s.y = tf32r(s.y); s.z = tf32r(s.z); s.w = tf32r(s.w);
    reinterpret_cast<float4*>(g_ctx)[f4] = s;
}

// ============================================================================
// K6: out = A @ ctx. M=8192, N=512, K=128 per batch. Block 128x128, KC=32.
// grid (4, 64, 8), ct fastest -> L2 dedups 4x A re-read. Operands pre-rounded.
// ============================================================================
__global__ __launch_bounds__(256, 2) void k_out(float* __restrict__ out) {
    extern __shared__ float sh[];
    const int tid = threadIdx.x, wid = tid >> 5;
    const int wm = wid >> 1, wn = wid & 1;
    const int ct = blockIdx.x, mt = blockIdx.y, b = blockIdx.z;
    const int m0 = mt * 128;

    wmma::fragment<wmma::accumulator, 16, 16, 8, float> c[2][4];
#pragma unroll
    for (int i = 0; i < 2; i++)
#pragma unroll
        for (int j = 0; j < 4; j++) wmma::fill_fragment(c[i][j], 0.0f);

    auto As = [&](int st) { return sh + st * 8832; };
    auto Bs = [&](int st) { return sh + st * 8832 + 4608; };

    auto load_tiles = [&](int st, int it) {
        const int kt = it * 32;
        float* a = As(st);
        float* bsh = Bs(st);
#pragma unroll
        for (int i = 0; i < 4; i++) {   // A: 128 x 32
            int idx = tid + i * 256;
            int row = idx >> 3, c4 = idx & 7;
            cp16(a + row * 36 + c4 * 4,
                 g_logits + ((size_t)b * Sdim + m0 + row) * Hdim + kt + c4 * 4);
        }
#pragma unroll
        for (int i = 0; i < 4; i++) {   // B: 32 x 128
            int idx = tid + i * 256;
            int row = idx >> 5, c4 = idx & 31;
            cp16(bsh + row * 132 + c4 * 4,
                 g_ctx + ((size_t)b * Hdim + kt + row) * Cdim + ct * 128 + c4 * 4);
        }
    };

    const int NIT = 4;
    load_tiles(0, 0); CP_COMMIT;
    load_tiles(1, 1); CP_COMMIT;
    for (int it = 0; it < NIT; ++it) {
        if (it + 2 < NIT) load_tiles((it + 2) % 3, it + 2);
        CP_COMMIT;
        CP_WAIT2;
        __syncthreads();
        const int st = it % 3;
#pragma unroll
        for (int kk = 0; kk < 32; kk += 8) {
            wmma::fragment<wmma::matrix_a, 16, 16, 8, wmma::precision::tf32,
                           wmma::row_major> a[2];
#pragma unroll
            for (int i = 0; i < 2; i++)
                wmma::load_matrix_sync(a[i], As(st) + (wm * 32 + i * 16) * 36 + kk, 36);
#pragma unroll
            for (int j = 0; j < 4; j++) {
                wmma::fragment<wmma::matrix_b, 16, 16, 8, wmma::precision::tf32,
                               wmma::row_major> bf;
                wmma::load_matrix_sync(bf, Bs(st) + kk * 132 + wn * 64 + j * 16, 132);
#pragma unroll
                for (int i = 0; i < 2; i++) wmma::mma_sync(c[i][j], a[i], bf, c[i][j]);
            }
        }
        __syncthreads();
    }
#pragma unroll
    for (int i = 0; i < 2; i++)
#pragma unroll
        for (int j = 0; j < 4; j++)
            wmma::store_matrix_sync(
                out + ((size_t)b * Sdim + m0 + wm * 32 + i * 16) * Cdim + ct * 128 +
                    wn * 64 + j * 16,
                c[i][j], Cdim, wmma::mem_row_major);
}

// ============================================================================
extern "C" void kernel_launch(void* const* d_in, const int* in_sizes, int n_in,
                              void* d_out, int out_size) {
    const float* x = (const float*)d_in[0];  // [B, S, C]
    const float* W = (const float*)d_in[1];  // [C, H]
    // d_in[2] (bias) cancels in softmax over S — skipped, exact.
    float* out = (float*)d_out;

    const size_t sh_logits = 26496 * 4;  // 3-stage pipeline (epilogue reuses it)
    const size_t sh_ctx    = 25344 * 4;
    const size_t sh_out    = 26496 * 4;
    cudaFuncSetAttribute(k_logits, cudaFuncAttributeMaxDynamicSharedMemorySize,
                         (int)sh_logits);
    cudaFuncSetAttribute(k_ctx, cudaFuncAttributeMaxDynamicSharedMemorySize,
                         (int)sh_ctx);
    cudaFuncSetAttribute(k_out, cudaFuncAttributeMaxDynamicSharedMemorySize,
                         (int)sh_out);

    k_logits<<<(Bdim * Sdim) / 128, 256, sh_logits>>>(x, W);
    k_comb<<<Bdim, 128>>>();
    k_aconv<<<8192, 256>>>();
    k_ctx<<<dim3(Cdim / 128, KSPLIT, Bdim), 256, sh_ctx>>>(x);
    k_reduce<<<512, 256>>>();
    k_out<<<dim3(Cdim / 128, Sdim / 128, Bdim), 256, sh_out>>>(out);
}

// round 5
// speedup vs baseline: 1.2724x; 1.0948x over previous
#include <cuda_runtime.h>
#include <mma.h>
#include <cstdint>

using namespace nvcuda;

#define Bdim 8
#define Sdim 8192
#define Cdim 512
#define Hdim 128

#define KSPLIT 8
#define SLICE  (Sdim/KSPLIT)   // 1024
#define NCH    32              // logits tiles (256 rows) per batch

// ---------------- scratch (static device globals) ---------------------------
__device__ float g_logits[(size_t)Bdim * Sdim * Hdim];                  // 33.5 MB (becomes A)
__device__ float g_wr[Cdim * Hdim];                                     // RN-rounded W
__device__ float g_part_m[Bdim * NCH * Hdim];
__device__ float g_part_s[Bdim * NCH * Hdim];
__device__ float g_stat_m[Bdim * Hdim];
__device__ float g_stat_inv[Bdim * Hdim];
__device__ float g_ctxT_part[(size_t)KSPLIT * Bdim * Cdim * Hdim];      // 16.8 MB
__device__ float g_ctxT[Bdim * Cdim * Hdim];                            // 2 MB  [b][c][h]

__device__ __forceinline__ float tf32r(float x) { return wmma::__float_to_tf32(x); }

__device__ __forceinline__ void cp16(float* smem_dst, const float* gmem_src) {
    unsigned s = (unsigned)__cvta_generic_to_shared(smem_dst);
    asm volatile("cp.async.cg.shared.global [%0], [%1], 16;\n" ::"r"(s), "l"(gmem_src));
}
#define CP_COMMIT asm volatile("cp.async.commit_group;\n")
#define CP_WAIT2  asm volatile("cp.async.wait_group 2;\n")

typedef wmma::fragment<wmma::accumulator, 16, 16, 8, float> AccFrag;
typedef wmma::fragment<wmma::matrix_a, 16, 16, 8, wmma::precision::tf32, wmma::row_major> AFragR;
typedef wmma::fragment<wmma::matrix_a, 16, 16, 8, wmma::precision::tf32, wmma::col_major> AFragC;
typedef wmma::fragment<wmma::matrix_b, 16, 16, 8, wmma::precision::tf32, wmma::row_major> BFragR;
typedef wmma::fragment<wmma::matrix_b, 16, 16, 8, wmma::precision::tf32, wmma::col_major> BFragC;

// K0: g_wr = RN-rounded W (tiny)
__global__ __launch_bounds__(256) void k_wr(const float* __restrict__ W) {
    int i = blockIdx.x * 256 + threadIdx.x;   // 65536 elems
    g_wr[i] = tf32r(W[i]);
}

// ============================================================================
// K1: logits = x @ W  (bias skipped: softmax over S cancels per-h constants)
// + fused per-256-row-tile column softmax stats.
// Block 256x128, warp tile 64x64 (8 warps), KC=32, 3-stage cp.async.
// ============================================================================
__global__ __launch_bounds__(256, 1) void k_logits(const float* __restrict__ x) {
    extern __shared__ float sh[];
    // stage stride = A 256*36 + B 32*132 = 13440 floats
    const int tid = threadIdx.x, wid = tid >> 5;
    const int wm = wid >> 1, wn = wid & 1;     // 4 x 2 positions of 64x64
    const int m0 = blockIdx.x * 256;

    AccFrag c[4][4];
#pragma unroll
    for (int i = 0; i < 4; i++)
#pragma unroll
        for (int j = 0; j < 4; j++) wmma::fill_fragment(c[i][j], 0.0f);

    auto As = [&](int st) { return sh + st * 13440; };
    auto Bs = [&](int st) { return sh + st * 13440 + 9216; };

    auto load_tiles = [&](int st, int it) {
        const int kt = it * 32;
        float* a = As(st);
        float* bsh = Bs(st);
#pragma unroll
        for (int i = 0; i < 8; i++) {      // A: 256x32 = 2048 f4
            int idx = tid + i * 256;
            int row = idx >> 3, c4 = idx & 7;
            cp16(a + row * 36 + c4 * 4, x + (size_t)(m0 + row) * Cdim + kt + c4 * 4);
        }
#pragma unroll
        for (int i = 0; i < 4; i++) {      // B: 32x128 = 1024 f4
            int idx = tid + i * 256;
            int row = idx >> 5, c4 = idx & 31;
            cp16(bsh + row * 132 + c4 * 4, g_wr + (size_t)(kt + row) * Hdim + c4 * 4);
        }
    };

    const int NIT = 16;
    load_tiles(0, 0); CP_COMMIT;
    load_tiles(1, 1); CP_COMMIT;
    for (int it = 0; it < NIT; ++it) {
        if (it + 2 < NIT) load_tiles((it + 2) % 3, it + 2);
        CP_COMMIT;
        CP_WAIT2;
        __syncthreads();
        const int st = it % 3;
#pragma unroll
        for (int kk = 0; kk < 32; kk += 8) {
            AFragR a[4];
#pragma unroll
            for (int i = 0; i < 4; i++) {
                wmma::load_matrix_sync(a[i], As(st) + (wm * 64 + i * 16) * 36 + kk, 36);
#pragma unroll
                for (int t = 0; t < a[i].num_elements; t++) a[i].x[t] = tf32r(a[i].x[t]);
            }
#pragma unroll
            for (int j = 0; j < 4; j++) {
                BFragR bf;
                wmma::load_matrix_sync(bf, Bs(st) + kk * 132 + wn * 64 + j * 16, 132);
#pragma unroll
                for (int i = 0; i < 4; i++) wmma::mma_sync(c[i][j], a[i], bf, c[i][j]);
            }
        }
        __syncthreads();
    }

    // epilogue: tile -> smem [256][132], write gmem + column stats
#pragma unroll
    for (int i = 0; i < 4; i++)
#pragma unroll
        for (int j = 0; j < 4; j++)
            wmma::store_matrix_sync(sh + (wm * 64 + i * 16) * 132 + wn * 64 + j * 16,
                                    c[i][j], 132, wmma::mem_row_major);
    __syncthreads();
#pragma unroll
    for (int i = 0; i < 32; i++) {
        int idx = tid + i * 256;
        int row = idx >> 5, c4 = idx & 31;
        float4 v = *reinterpret_cast<float4*>(sh + row * 132 + c4 * 4);
        *reinterpret_cast<float4*>(g_logits + (size_t)(m0 + row) * Hdim + c4 * 4) = v;
    }
    {
        float* pm = sh + 33792;
        float* ps = sh + 34048;
        const int col = tid & 127, half = tid >> 7;
        float m = -1e30f;
#pragma unroll 8
        for (int r = half * 128; r < half * 128 + 128; r++)
            m = fmaxf(m, sh[r * 132 + col]);
        float s = 0.0f;
#pragma unroll 8
        for (int r = half * 128; r < half * 128 + 128; r++)
            s += __expf(sh[r * 132 + col] - m);
        pm[tid] = m; ps[tid] = s;
        __syncthreads();
        if (half == 0) {
            float m1 = pm[col + 128], s1 = ps[col + 128];
            float mn = fmaxf(m, m1);
            float sc = s * __expf(m - mn) + s1 * __expf(m1 - mn);
            const int b = blockIdx.x >> 5, ch = blockIdx.x & 31;
            g_part_m[((size_t)b * NCH + ch) * Hdim + col] = mn;
            g_part_s[((size_t)b * NCH + ch) * Hdim + col] = sc;
        }
    }
}

// K2: combine chunk stats
__global__ __launch_bounds__(128) void k_comb() {
    const int b = blockIdx.x, h = threadIdx.x;
    float m = -1e30f, s = 0.0f;
    for (int ch = 0; ch < NCH; ch++) {
        float pmv = g_part_m[((size_t)b * NCH + ch) * Hdim + h];
        float psv = g_part_s[((size_t)b * NCH + ch) * Hdim + h];
        float mn = fmaxf(m, pmv);
        s = s * __expf(m - mn) + psv * __expf(pmv - mn);
        m = mn;
    }
    g_stat_m[b * Hdim + h] = m;
    g_stat_inv[b * Hdim + h] = 1.0f / s;
}

// K3: A = tf32_RN(exp(l - m) * inv), in place over g_logits
__global__ __launch_bounds__(256) void k_aconv() {
    const size_t f4 = (size_t)blockIdx.x * 256 + threadIdx.x;  // 2,097,152 total
    const size_t e0 = f4 * 4;
    const int b = (int)(e0 >> 20);
    const int h0 = (int)(e0 & 127);
    float4 l = reinterpret_cast<float4*>(g_logits)[f4];
    const float* sm = g_stat_m + b * Hdim + h0;
    const float* si = g_stat_inv + b * Hdim + h0;
    l.x = tf32r(__expf(l.x - __ldg(sm + 0)) * __ldg(si + 0));
    l.y = tf32r(__expf(l.y - __ldg(sm + 1)) * __ldg(si + 1));
    l.z = tf32r(__expf(l.z - __ldg(sm + 2)) * __ldg(si + 2));
    l.w = tf32r(__expf(l.w - __ldg(sm + 3)) * __ldg(si + 3));
    reinterpret_cast<float4*>(g_logits)[f4] = l;
}

// ============================================================================
// K4: ctxT_part[ks][b] = (x^T @ A) over a K-slice of 1024 s-rows.
// Output tile ctx^T [c=256][h=128]: M=c (col-major A frags of x), N=h (A mat).
// Block 256x128, warp 64x64, KC=32, 3-stage. grid (2 ct, 8 ks, 8 b) = 128.
// x enters truncated-to-tf32 (cp.async raw); g_logits pre-rounded.
// ============================================================================
__global__ __launch_bounds__(256, 1) void k_ctx(const float* __restrict__ x) {
    extern __shared__ float sh[];
    // stage stride = Ax 32*260 + Ba 32*132 = 12544 floats
    const int tid = threadIdx.x, wid = tid >> 5;
    const int wm = wid >> 1, wn = wid & 1;
    const int ct = blockIdx.x, ks = blockIdx.y, b = blockIdx.z;
    const int sbase = ks * SLICE;
    const int c0 = ct * 256;

    AccFrag c[4][4];
#pragma unroll
    for (int i = 0; i < 4; i++)
#pragma unroll
        for (int j = 0; j < 4; j++) wmma::fill_fragment(c[i][j], 0.0f);

    auto As = [&](int st) { return sh + st * 12544; };          // x tile [32 s][260]
    auto Bs = [&](int st) { return sh + st * 12544 + 8320; };   // A tile [32 s][132]

    auto load_tiles = [&](int st, int it) {
        const int s0 = sbase + it * 32;
        float* a = As(st);
        float* bsh = Bs(st);
#pragma unroll
        for (int i = 0; i < 8; i++) {      // x: 32 x 256 = 2048 f4
            int idx = tid + i * 256;
            int row = idx >> 6, c4 = idx & 63;
            cp16(a + row * 260 + c4 * 4,
                 x + ((size_t)b * Sdim + s0 + row) * Cdim + c0 + c4 * 4);
        }
#pragma unroll
        for (int i = 0; i < 4; i++) {      // A: 32 x 128 = 1024 f4
            int idx = tid + i * 256;
            int row = idx >> 5, c4 = idx & 31;
            cp16(bsh + row * 132 + c4 * 4,
                 g_logits + ((size_t)b * Sdim + s0 + row) * Hdim + c4 * 4);
        }
    };

    const int NIT = SLICE / 32;   // 32
    load_tiles(0, 0); CP_COMMIT;
    load_tiles(1, 1); CP_COMMIT;
    for (int it = 0; it < NIT; ++it) {
        if (it + 2 < NIT) load_tiles((it + 2) % 3, it + 2);
        CP_COMMIT;
        CP_WAIT2;
        __syncthreads();
        const int st = it % 3;
#pragma unroll
        for (int kk = 0; kk < 32; kk += 8) {
            AFragC a[4];
#pragma unroll
            for (int i = 0; i < 4; i++)
                wmma::load_matrix_sync(a[i], As(st) + kk * 260 + wm * 64 + i * 16, 260);
#pragma unroll
            for (int j = 0; j < 4; j++) {
                BFragR bf;
                wmma::load_matrix_sync(bf, Bs(st) + kk * 132 + wn * 64 + j * 16, 132);
#pragma unroll
                for (int i = 0; i < 4; i++) wmma::mma_sync(c[i][j], a[i], bf, c[i][j]);
            }
        }
        __syncthreads();
    }
#pragma unroll
    for (int i = 0; i < 4; i++)
#pragma unroll
        for (int j = 0; j < 4; j++)
            wmma::store_matrix_sync(
                g_ctxT_part + (((size_t)ks * Bdim + b) * Cdim + c0 + wm * 64 + i * 16) * Hdim +
                    wn * 64 + j * 16,
                c[i][j], Hdim, wmma::mem_row_major);
}

// K5: deterministic split-K reduce -> g_ctxT [b][c][h], RN-rounded to tf32
__global__ __launch_bounds__(256) void k_reduce() {
    const size_t f4 = (size_t)blockIdx.x * 256 + threadIdx.x;  // 131072 total
    float4 s = make_float4(0.f, 0.f, 0.f, 0.f);
#pragma unroll
    for (int p = 0; p < KSPLIT; p++) {
        float4 v = reinterpret_cast<float4*>(
            g_ctxT_part + (size_t)p * Bdim * Cdim * Hdim)[f4];
        s.x += v.x; s.y += v.y; s.z += v.z; s.w += v.w;
    }
    s.x = tf32r(s.x); s.y = tf32r(s.y); s.z = tf32r(s.z); s.w = tf32r(s.w);
    reinterpret_cast<float4*>(g_ctxT)[f4] = s;
}

// ============================================================================
// K6: out = A @ ctx. M=8192(s), N=512(c), K=128(h) per batch.
// Block 256x128, warp 64x64. B = ctx^T consumed via col-major frags.
// grid (4 ct, 32 mt, 8 b), ct fastest.
// ============================================================================
__global__ __launch_bounds__(256, 1) void k_out(float* __restrict__ out) {
    extern __shared__ float sh[];
    // stage stride = A 256*36 + B 128*36 = 13824 floats
    const int tid = threadIdx.x, wid = tid >> 5;
    const int wm = wid >> 1, wn = wid & 1;
    const int ct = blockIdx.x, mt = blockIdx.y, b = blockIdx.z;
    const int m0 = mt * 256, c0 = ct * 128;

    AccFrag c[4][4];
#pragma unroll
    for (int i = 0; i < 4; i++)
#pragma unroll
        for (int j = 0; j < 4; j++) wmma::fill_fragment(c[i][j], 0.0f);

    auto As = [&](int st) { return sh + st * 13824; };          // A [256 s][36]
    auto Bs = [&](int st) { return sh + st * 13824 + 9216; };   // ctxT [128 c][36]

    auto load_tiles = [&](int st, int it) {
        const int kt = it * 32;
        float* a = As(st);
        float* bsh = Bs(st);
#pragma unroll
        for (int i = 0; i < 8; i++) {      // A: 256x32 = 2048 f4
            int idx = tid + i * 256;
            int row = idx >> 3, c4 = idx & 7;
            cp16(a + row * 36 + c4 * 4,
                 g_logits + ((size_t)b * Sdim + m0 + row) * Hdim + kt + c4 * 4);
        }
#pragma unroll
        for (int i = 0; i < 4; i++) {      // ctxT: 128 rows(c) x 32 (h) = 1024 f4
            int idx = tid + i * 256;
            int row = idx >> 3, c4 = idx & 7;
            cp16(bsh + row * 36 + c4 * 4,
                 g_ctxT + ((size_t)b * Cdim + c0 + row) * Hdim + kt + c4 * 4);
        }
    };

    const int NIT = 4;
    load_tiles(0, 0); CP_COMMIT;
    load_tiles(1, 1); CP_COMMIT;
    for (int it = 0; it < NIT; ++it) {
        if (it + 2 < NIT) load_tiles((it + 2) % 3, it + 2);
        CP_COMMIT;
        CP_WAIT2;
        __syncthreads();
        const int st = it % 3;
#pragma unroll
        for (int kk = 0; kk < 32; kk += 8) {
            AFragR a[4];
#pragma unroll
            for (int i = 0; i < 4; i++)
                wmma::load_matrix_sync(a[i], As(st) + (wm * 64 + i * 16) * 36 + kk, 36);
#pragma unroll
            for (int j = 0; j < 4; j++) {
                BFragC bf;   // B[k=h][n=c] at Bs[c][h] -> col-major, ldm 36
                wmma::load_matrix_sync(bf, Bs(st) + (wn * 64 + j * 16) * 36 + kk, 36);
#pragma unroll
                for (int i = 0; i < 4; i++) wmma::mma_sync(c[i][j], a[i], bf, c[i][j]);
            }
        }
        __syncthreads();
    }
#pragma unroll
    for (int i = 0; i < 4; i++)
#pragma unroll
        for (int j = 0; j < 4; j++)
            wmma::store_matrix_sync(
                out + ((size_t)b * Sdim + m0 + wm * 64 + i * 16) * Cdim + c0 +
                    wn * 64 + j * 16,
                c[i][j], Cdim, wmma::mem_row_major);
}

// ============================================================================
extern "C" void kernel_launch(void* const* d_in, const int* in_sizes, int n_in,
                              void* d_out, int out_size) {
    const float* x = (const float*)d_in[0];  // [B, S, C]
    const float* W = (const float*)d_in[1];  // [C, H]
    // d_in[2] (bias) cancels in softmax over S — skipped, exact.
    float* out = (float*)d_out;

    const size_t sh_logits = 40320 * 4;   // 3 stages; epilogue reuses (34304 used)
    const size_t sh_ctx    = 37632 * 4;
    const size_t sh_out    = 41472 * 4;
    cudaFuncSetAttribute(k_logits, cudaFuncAttributeMaxDynamicSharedMemorySize,
                         (int)sh_logits);
    cudaFuncSetAttribute(k_ctx, cudaFuncAttributeMaxDynamicSharedMemorySize,
                         (int)sh_ctx);
    cudaFuncSetAttribute(k_out, cudaFuncAttributeMaxDynamicSharedMemorySize,
                         (int)sh_out);

    k_wr<<<Cdim * Hdim / 256, 256>>>(W);
    k_logits<<<(Bdim * Sdim) / 256, 256, sh_logits>>>(x);
    k_comb<<<Bdim, 128>>>();
    k_aconv<<<8192, 256>>>();
    k_ctx<<<dim3(Cdim / 256, KSPLIT, Bdim), 256, sh_ctx>>>(x);
    k_reduce<<<512, 256>>>();
    k_out<<<dim3(Cdim / 128, Sdim / 256, Bdim), 256, sh_out>>>(out);
}

// round 6
// speedup vs baseline: 2.6151x; 2.0552x over previous
#include <cuda_runtime.h>
#include <cuda_fp16.h>
#include <mma.h>
#include <cstdint>

using namespace nvcuda;

#define Bdim 8
#define Sdim 8192
#define Cdim 512
#define Hdim 128

#define KSPLIT 8
#define SLICE  (Sdim/KSPLIT)   // 1024
#define NCH    32              // logits tiles (256 rows) per batch

// ---------------- scratch (static device globals) ---------------------------
__device__ __half g_xh[(size_t)Bdim * Sdim * Cdim];                     // 67 MB
__device__ __half g_wh[Cdim * Hdim];
__device__ float  g_logits[(size_t)Bdim * Sdim * Hdim];                 // 33.5 MB
__device__ __half g_ah[(size_t)Bdim * Sdim * Hdim];                     // 16.8 MB
__device__ float  g_part_m[Bdim * NCH * Hdim];
__device__ float  g_part_s[Bdim * NCH * Hdim];
__device__ float  g_stat_m[Bdim * Hdim];
__device__ float  g_stat_inv[Bdim * Hdim];
__device__ float  g_ctxT_part[(size_t)KSPLIT * Bdim * Cdim * Hdim];     // 16.8 MB
__device__ __half g_cth[Bdim * Cdim * Hdim];                            // 1 MB [b][c][h]

__device__ __forceinline__ void cp16(void* smem_dst, const void* gmem_src) {
    unsigned s = (unsigned)__cvta_generic_to_shared(smem_dst);
    asm volatile("cp.async.cg.shared.global [%0], [%1], 16;\n" ::"r"(s), "l"(gmem_src));
}
#define CP_COMMIT asm volatile("cp.async.commit_group;\n")
#define CP_WAIT2  asm volatile("cp.async.wait_group 2;\n")

typedef wmma::fragment<wmma::accumulator, 16, 16, 16, float> HAcc;
typedef wmma::fragment<wmma::matrix_a, 16, 16, 16, __half, wmma::row_major> HAFragR;
typedef wmma::fragment<wmma::matrix_a, 16, 16, 16, __half, wmma::col_major> HAFragC;
typedef wmma::fragment<wmma::matrix_b, 16, 16, 16, __half, wmma::row_major> HBFragR;
typedef wmma::fragment<wmma::matrix_b, 16, 16, 16, __half, wmma::col_major> HBFragC;

// K-1: x -> fp16 (RN)
__global__ __launch_bounds__(256) void k_prep(const float* __restrict__ x) {
    const size_t f4 = (size_t)blockIdx.x * 256 + threadIdx.x;   // 8,388,608
    float4 v = reinterpret_cast<const float4*>(x)[f4];
    __half2* dst = reinterpret_cast<__half2*>(g_xh) + f4 * 2;
    dst[0] = __floats2half2_rn(v.x, v.y);
    dst[1] = __floats2half2_rn(v.z, v.w);
}

// K0: W -> fp16 (RN)
__global__ __launch_bounds__(256) void k_wr(const float* __restrict__ W) {
    int i = blockIdx.x * 256 + threadIdx.x;    // 65536
    g_wh[i] = __float2half_rn(W[i]);
}

// ============================================================================
// K1: logits = x @ W  (bias skipped: softmax over S cancels per-h constants)
// fp16 operands, fp32 accum. Block 256x128, warp 64x64, KC=32, 3-stage.
// Fused per-256-row-tile column softmax stats.
// ============================================================================
__global__ __launch_bounds__(256, 1) void k_logits() {
    extern __shared__ char shc[];
    __half* shh = reinterpret_cast<__half*>(shc);
    float* shf = reinterpret_cast<float*>(shc);
    // stage stride = A 256*40 + B 32*136 = 14592 halves
    const int tid = threadIdx.x, wid = tid >> 5;
    const int wm = wid >> 1, wn = wid & 1;
    const int m0 = blockIdx.x * 256;

    HAcc c[4][4];
#pragma unroll
    for (int i = 0; i < 4; i++)
#pragma unroll
        for (int j = 0; j < 4; j++) wmma::fill_fragment(c[i][j], 0.0f);

    auto As = [&](int st) { return shh + st * 14592; };
    auto Bs = [&](int st) { return shh + st * 14592 + 10240; };

    auto load_tiles = [&](int st, int it) {
        const int kt = it * 32;
        __half* a = As(st);
        __half* bsh = Bs(st);
#pragma unroll
        for (int i = 0; i < 4; i++) {      // A: 256x32 halves = 1024 chunks of 8
            int idx = tid + i * 256;
            int row = idx >> 2, c8 = idx & 3;
            cp16(a + row * 40 + c8 * 8, g_xh + (size_t)(m0 + row) * Cdim + kt + c8 * 8);
        }
#pragma unroll
        for (int i = 0; i < 2; i++) {      // B: 32x128 halves = 512 chunks
            int idx = tid + i * 256;
            int row = idx >> 4, c8 = idx & 15;
            cp16(bsh + row * 136 + c8 * 8, g_wh + (size_t)(kt + row) * Hdim + c8 * 8);
        }
    };

    const int NIT = 16;
    load_tiles(0, 0); CP_COMMIT;
    load_tiles(1, 1); CP_COMMIT;
    for (int it = 0; it < NIT; ++it) {
        if (it + 2 < NIT) load_tiles((it + 2) % 3, it + 2);
        CP_COMMIT;
        CP_WAIT2;
        __syncthreads();
        const int st = it % 3;
#pragma unroll
        for (int kk = 0; kk < 32; kk += 16) {
            HAFragR a[4];
#pragma unroll
            for (int i = 0; i < 4; i++)
                wmma::load_matrix_sync(a[i], As(st) + (wm * 64 + i * 16) * 40 + kk, 40);
#pragma unroll
            for (int j = 0; j < 4; j++) {
                HBFragR bf;
                wmma::load_matrix_sync(bf, Bs(st) + kk * 136 + wn * 64 + j * 16, 136);
#pragma unroll
                for (int i = 0; i < 4; i++) wmma::mma_sync(c[i][j], a[i], bf, c[i][j]);
            }
        }
        __syncthreads();
    }

    // epilogue: tile -> smem fp32 [256][132], write gmem + column stats
#pragma unroll
    for (int i = 0; i < 4; i++)
#pragma unroll
        for (int j = 0; j < 4; j++)
            wmma::store_matrix_sync(shf + (wm * 64 + i * 16) * 132 + wn * 64 + j * 16,
                                    c[i][j], 132, wmma::mem_row_major);
    __syncthreads();
#pragma unroll
    for (int i = 0; i < 32; i++) {
        int idx = tid + i * 256;
        int row = idx >> 5, c4 = idx & 31;
        float4 v = *reinterpret_cast<float4*>(shf + row * 132 + c4 * 4);
        *reinterpret_cast<float4*>(g_logits + (size_t)(m0 + row) * Hdim + c4 * 4) = v;
    }
    {
        float* pm = shf + 33792;
        float* ps = shf + 34048;
        const int col = tid & 127, half = tid >> 7;
        float m = -1e30f;
#pragma unroll 8
        for (int r = half * 128; r < half * 128 + 128; r++)
            m = fmaxf(m, shf[r * 132 + col]);
        float s = 0.0f;
#pragma unroll 8
        for (int r = half * 128; r < half * 128 + 128; r++)
            s += __expf(shf[r * 132 + col] - m);
        pm[tid] = m; ps[tid] = s;
        __syncthreads();
        if (half == 0) {
            float m1 = pm[col + 128], s1 = ps[col + 128];
            float mn = fmaxf(m, m1);
            float sc = s * __expf(m - mn) + s1 * __expf(m1 - mn);
            const int b = blockIdx.x >> 5, ch = blockIdx.x & 31;
            g_part_m[((size_t)b * NCH + ch) * Hdim + col] = mn;
            g_part_s[((size_t)b * NCH + ch) * Hdim + col] = sc;
        }
    }
}

// K2: combine chunk stats
__global__ __launch_bounds__(128) void k_comb() {
    const int b = blockIdx.x, h = threadIdx.x;
    float m = -1e30f, s = 0.0f;
    for (int ch = 0; ch < NCH; ch++) {
        float pmv = g_part_m[((size_t)b * NCH + ch) * Hdim + h];
        float psv = g_part_s[((size_t)b * NCH + ch) * Hdim + h];
        float mn = fmaxf(m, pmv);
        s = s * __expf(m - mn) + psv * __expf(pmv - mn);
        m = mn;
    }
    g_stat_m[b * Hdim + h] = m;
    g_stat_inv[b * Hdim + h] = 1.0f / s;
}

// K3: A = fp16_RN(exp(l - m) * inv)  (fp32 logits -> fp16 A)
__global__ __launch_bounds__(256) void k_aconv() {
    const size_t f4 = (size_t)blockIdx.x * 256 + threadIdx.x;  // 2,097,152
    const size_t e0 = f4 * 4;
    const int b = (int)(e0 >> 20);
    const int h0 = (int)(e0 & 127);
    float4 l = reinterpret_cast<float4*>(g_logits)[f4];
    const float* sm = g_stat_m + b * Hdim + h0;
    const float* si = g_stat_inv + b * Hdim + h0;
    float a0 = __expf(l.x - __ldg(sm + 0)) * __ldg(si + 0);
    float a1 = __expf(l.y - __ldg(sm + 1)) * __ldg(si + 1);
    float a2 = __expf(l.z - __ldg(sm + 2)) * __ldg(si + 2);
    float a3 = __expf(l.w - __ldg(sm + 3)) * __ldg(si + 3);
    __half2* dst = reinterpret_cast<__half2*>(g_ah) + f4 * 2;
    dst[0] = __floats2half2_rn(a0, a1);
    dst[1] = __floats2half2_rn(a2, a3);
}

// ============================================================================
// K4: ctxT_part[ks][b] = x^T @ A over a 1024-row s-slice. fp16 operands.
// Output ctx^T tile [c=256][h=128]. Block warp 64x64, KC=32, 3-stage.
// grid (2 ct, 8 ks, 8 b) = 128 blocks.
// ============================================================================
__global__ __launch_bounds__(256, 1) void k_ctx() {
    extern __shared__ char shc[];
    __half* shh = reinterpret_cast<__half*>(shc);
    // stage stride = x 32*264 + A 32*136 = 12800 halves
    const int tid = threadIdx.x, wid = tid >> 5;
    const int wm = wid >> 1, wn = wid & 1;
    const int ct = blockIdx.x, ks = blockIdx.y, b = blockIdx.z;
    const int sbase = ks * SLICE;
    const int c0 = ct * 256;

    HAcc c[4][4];
#pragma unroll
    for (int i = 0; i < 4; i++)
#pragma unroll
        for (int j = 0; j < 4; j++) wmma::fill_fragment(c[i][j], 0.0f);

    auto Xs = [&](int st) { return shh + st * 12800; };           // [32 s][264]
    auto Bs = [&](int st) { return shh + st * 12800 + 8448; };    // [32 s][136]

    auto load_tiles = [&](int st, int it) {
        const int s0 = sbase + it * 32;
        __half* xs = Xs(st);
        __half* bsh = Bs(st);
#pragma unroll
        for (int i = 0; i < 4; i++) {      // x: 32x256 halves = 1024 chunks
            int idx = tid + i * 256;
            int row = idx >> 5, c8 = idx & 31;
            cp16(xs + row * 264 + c8 * 8,
                 g_xh + ((size_t)b * Sdim + s0 + row) * Cdim + c0 + c8 * 8);
        }
#pragma unroll
        for (int i = 0; i < 2; i++) {      // A: 32x128 halves = 512 chunks
            int idx = tid + i * 256;
            int row = idx >> 4, c8 = idx & 15;
            cp16(bsh + row * 136 + c8 * 8,
                 g_ah + ((size_t)b * Sdim + s0 + row) * Hdim + c8 * 8);
        }
    };

    const int NIT = SLICE / 32;   // 32
    load_tiles(0, 0); CP_COMMIT;
    load_tiles(1, 1); CP_COMMIT;
    for (int it = 0; it < NIT; ++it) {
        if (it + 2 < NIT) load_tiles((it + 2) % 3, it + 2);
        CP_COMMIT;
        CP_WAIT2;
        __syncthreads();
        const int st = it % 3;
#pragma unroll
        for (int kk = 0; kk < 32; kk += 16) {
            HAFragC a[4];    // M=c from x[s][c] col-major view
#pragma unroll
            for (int i = 0; i < 4; i++)
                wmma::load_matrix_sync(a[i], Xs(st) + kk * 264 + wm * 64 + i * 16, 264);
#pragma unroll
            for (int j = 0; j < 4; j++) {
                HBFragR bf;
                wmma::load_matrix_sync(bf, Bs(st) + kk * 136 + wn * 64 + j * 16, 136);
#pragma unroll
                for (int i = 0; i < 4; i++) wmma::mma_sync(c[i][j], a[i], bf, c[i][j]);
            }
        }
        __syncthreads();
    }
#pragma unroll
    for (int i = 0; i < 4; i++)
#pragma unroll
        for (int j = 0; j < 4; j++)
            wmma::store_matrix_sync(
                g_ctxT_part + (((size_t)ks * Bdim + b) * Cdim + c0 + wm * 64 + i * 16) * Hdim +
                    wn * 64 + j * 16,
                c[i][j], Hdim, wmma::mem_row_major);
}

// K5: deterministic split-K reduce -> g_cth fp16 [b][c][h]
__global__ __launch_bounds__(256) void k_reduce() {
    const size_t f4 = (size_t)blockIdx.x * 256 + threadIdx.x;  // 131072
    float4 s = make_float4(0.f, 0.f, 0.f, 0.f);
#pragma unroll
    for (int p = 0; p < KSPLIT; p++) {
        float4 v = reinterpret_cast<float4*>(
            g_ctxT_part + (size_t)p * Bdim * Cdim * Hdim)[f4];
        s.x += v.x; s.y += v.y; s.z += v.z; s.w += v.w;
    }
    __half2* dst = reinterpret_cast<__half2*>(g_cth) + f4 * 2;
    dst[0] = __floats2half2_rn(s.x, s.y);
    dst[1] = __floats2half2_rn(s.z, s.w);
}

// ============================================================================
// K6: out = A @ ctx. M=8192(s), N=512(c), K=128(h). fp16 operands.
// B = ctx^T fp16 consumed col-major. Block 256x128, warp 64x64, KC=32.
// grid (4 ct, 32 mt, 8 b), ct fastest.
// ============================================================================
__global__ __launch_bounds__(256, 1) void k_out(float* __restrict__ out) {
    extern __shared__ char shc[];
    __half* shh = reinterpret_cast<__half*>(shc);
    // stage stride = A 256*40 + ctxT 128*40 = 15360 halves
    const int tid = threadIdx.x, wid = tid >> 5;
    const int wm = wid >> 1, wn = wid & 1;
    const int ct = blockIdx.x, mt = blockIdx.y, b = blockIdx.z;
    const int m0 = mt * 256, c0 = ct * 128;

    HAcc c[4][4];
#pragma unroll
    for (int i = 0; i < 4; i++)
#pragma unroll
        for (int j = 0; j < 4; j++) wmma::fill_fragment(c[i][j], 0.0f);

    auto As = [&](int st) { return shh + st * 15360; };           // [256 s][40]
    auto Bs = [&](int st) { return shh + st * 15360 + 10240; };   // [128 c][40]

    auto load_tiles = [&](int st, int it) {
        const int kt = it * 32;
        __half* a = As(st);
        __half* bsh = Bs(st);
#pragma unroll
        for (int i = 0; i < 4; i++) {      // A: 256x32 halves = 1024 chunks
            int idx = tid + i * 256;
            int row = idx >> 2, c8 = idx & 3;
            cp16(a + row * 40 + c8 * 8,
                 g_ah + ((size_t)b * Sdim + m0 + row) * Hdim + kt + c8 * 8);
        }
#pragma unroll
        for (int i = 0; i < 2; i++) {      // ctxT: 128x32 halves = 512 chunks
            int idx = tid + i * 256;
            int row = idx >> 2, c8 = idx & 3;
            cp16(bsh + row * 40 + c8 * 8,
                 g_cth + ((size_t)b * Cdim + c0 + row) * Hdim + kt + c8 * 8);
        }
    };

    const int NIT = 4;
    load_tiles(0, 0); CP_COMMIT;
    load_tiles(1, 1); CP_COMMIT;
    for (int it = 0; it < NIT; ++it) {
        if (it + 2 < NIT) load_tiles((it + 2) % 3, it + 2);
        CP_COMMIT;
        CP_WAIT2;
        __syncthreads();
        const int st = it % 3;
#pragma unroll
        for (int kk = 0; kk < 32; kk += 16) {
            HAFragR a[4];
#pragma unroll
            for (int i = 0; i < 4; i++)
                wmma::load_matrix_sync(a[i], As(st) + (wm * 64 + i * 16) * 40 + kk, 40);
#pragma unroll
            for (int j = 0; j < 4; j++) {
                HBFragC bf;   // B[k=h][n=c] at Bs[c][h] -> col-major, ldm 40
                wmma::load_matrix_sync(bf, Bs(st) + (wn * 64 + j * 16) * 40 + kk, 40);
#pragma unroll
                for (int i = 0; i < 4; i++) wmma::mma_sync(c[i][j], a[i], bf, c[i][j]);
            }
        }
        __syncthreads();
    }
#pragma unroll
    for (int i = 0; i < 4; i++)
#pragma unroll
        for (int j = 0; j < 4; j++)
            wmma::store_matrix_sync(
                out + ((size_t)b * Sdim + m0 + wm * 64 + i * 16) * Cdim + c0 +
                    wn * 64 + j * 16,
                c[i][j], Cdim, wmma::mem_row_major);
}

// ============================================================================
extern "C" void kernel_launch(void* const* d_in, const int* in_sizes, int n_in,
                              void* d_out, int out_size) {
    const float* x = (const float*)d_in[0];  // [B, S, C]
    const float* W = (const float*)d_in[1];  // [C, H]
    // d_in[2] (bias) cancels in softmax over S — skipped, exact.
    float* out = (float*)d_out;

    const size_t sh_logits = 137216;   // epilogue fp32 tile dominates
    const size_t sh_ctx    = 76800;
    const size_t sh_out    = 92160;
    cudaFuncSetAttribute(k_logits, cudaFuncAttributeMaxDynamicSharedMemorySize,
                         (int)sh_logits);
    cudaFuncSetAttribute(k_ctx, cudaFuncAttributeMaxDynamicSharedMemorySize,
                         (int)sh_ctx);
    cudaFuncSetAttribute(k_out, cudaFuncAttributeMaxDynamicSharedMemorySize,
                         (int)sh_out);

    k_prep<<<32768, 256>>>(x);
    k_wr<<<Cdim * Hdim / 256, 256>>>(W);
    k_logits<<<(Bdim * Sdim) / 256, 256, sh_logits>>>();
    k_comb<<<Bdim, 128>>>();
    k_aconv<<<8192, 256>>>();
    k_ctx<<<dim3(Cdim / 256, KSPLIT, Bdim), 256, sh_ctx>>>();
    k_reduce<<<512, 256>>>();
    k_out<<<dim3(Cdim / 128, Sdim / 256, Bdim), 256, sh_out>>>(out);
}

// round 8
// speedup vs baseline: 2.9584x; 1.1313x over previous
#include <cuda_runtime.h>
#include <cuda_fp16.h>
#include <mma.h>
#include <cstdint>

using namespace nvcuda;

#define Bdim 8
#define Sdim 8192
#define Cdim 512
#define Hdim 128

#define KSPLIT 8
#define SLICE  (Sdim/KSPLIT)   // 1024
#define NCH    32              // logits tiles (256 rows) per batch

// ---------------- scratch (static device globals) ---------------------------
__device__ __half g_xh[(size_t)Bdim * Sdim * Cdim];                     // 67 MB
__device__ __half g_wh[Cdim * Hdim];
__device__ float  g_logits[(size_t)Bdim * Sdim * Hdim];                 // 33.5 MB
__device__ __half g_ah[(size_t)Bdim * Sdim * Hdim];                     // 16.8 MB
__device__ float  g_part_m[Bdim * NCH * Hdim];
__device__ float  g_part_s[Bdim * NCH * Hdim];
__device__ float  g_ctxT_part[(size_t)KSPLIT * Bdim * Cdim * Hdim];     // 16.8 MB
__device__ __half g_cth[Bdim * Cdim * Hdim];                            // 1 MB [b][c][h]

__device__ __forceinline__ void cp16(void* smem_dst, const void* gmem_src) {
    unsigned s = (unsigned)__cvta_generic_to_shared(smem_dst);
    asm volatile("cp.async.cg.shared.global [%0], [%1], 16;\n" ::"r"(s), "l"(gmem_src));
}
#define CP_COMMIT asm volatile("cp.async.commit_group;\n")
#define CP_WAIT2  asm volatile("cp.async.wait_group 2;\n")

typedef wmma::fragment<wmma::accumulator, 16, 16, 16, float> HAcc;
typedef wmma::fragment<wmma::matrix_a, 16, 16, 16, __half, wmma::row_major> HAFragR;
typedef wmma::fragment<wmma::matrix_a, 16, 16, 16, __half, wmma::col_major> HAFragC;
typedef wmma::fragment<wmma::matrix_b, 16, 16, 16, __half, wmma::row_major> HBFragR;
typedef wmma::fragment<wmma::matrix_b, 16, 16, 16, __half, wmma::col_major> HBFragC;

__device__ __forceinline__ uint32_t h2u(__half2 h) {
    uint32_t u;
    *reinterpret_cast<__half2*>(&u) = h;
    return u;
}

// K0: W -> fp16 (RN)
__global__ __launch_bounds__(256) void k_wr(const float* __restrict__ W) {
    int i = blockIdx.x * 256 + threadIdx.x;    // 65536
    g_wh[i] = __float2half_rn(W[i]);
}

// ============================================================================
// K1: logits = x @ W  (bias skipped: softmax over S cancels per-h constants)
// x streams in as fp32; per-chunk convert produces the fp16 MMA tile AND
// writes g_xh (replaces the former k_prep pass). Fused column softmax stats.
// Block 256x128, warp 64x64, KC=32, 3-stage cp.async on the fp32 tiles.
// ============================================================================
__global__ __launch_bounds__(256, 1) void k_logits(const float* __restrict__ x) {
    extern __shared__ char shc[];
    float* shf = reinterpret_cast<float*>(shc);
    __half* shh = reinterpret_cast<__half*>(shc);
    // layout (halves): A fp32 stages [3][256][36] = 55296 h-equivalents,
    // W fp16 stages [3][32][136] @55296, fp16 A buf [256][40] @68352
    const int tid = threadIdx.x, wid = tid >> 5;
    const int wm = wid >> 1, wn = wid & 1;
    const int m0 = blockIdx.x * 256;

    HAcc c[4][4];
#pragma unroll
    for (int i = 0; i < 4; i++)
#pragma unroll
        for (int j = 0; j < 4; j++) wmma::fill_fragment(c[i][j], 0.0f);

    auto Af = [&](int st) { return shf + st * 9216; };            // fp32 [256][36]
    auto Ws = [&](int st) { return shh + 55296 + st * 4352; };    // fp16 [32][136]
    __half* hbuf = shh + 68352;                                   // fp16 [256][40]

    auto load_tiles = [&](int st, int it) {
        const int kt = it * 32;
        float* a = Af(st);
        __half* w = Ws(st);
#pragma unroll
        for (int i = 0; i < 8; i++) {      // x fp32: 256x32 = 2048 f4
            int idx = tid + i * 256;
            int row = idx >> 3, c4 = idx & 7;
            cp16(a + row * 36 + c4 * 4, x + (size_t)(m0 + row) * Cdim + kt + c4 * 4);
        }
#pragma unroll
        for (int i = 0; i < 2; i++) {      // W fp16: 32x128 halves
            int idx = tid + i * 256;
            int row = idx >> 4, c8 = idx & 15;
            cp16(w + row * 136 + c8 * 8, g_wh + (size_t)(kt + row) * Hdim + c8 * 8);
        }
    };

    const int NIT = 16;
    load_tiles(0, 0); CP_COMMIT;
    load_tiles(1, 1); CP_COMMIT;
    for (int it = 0; it < NIT; ++it) {
        if (it + 2 < NIT) load_tiles((it + 2) % 3, it + 2);
        CP_COMMIT;
        CP_WAIT2;
        __syncthreads();
        const int st = it % 3;
        const int kt = it * 32;
        // convert fp32 tile -> fp16 buf + write g_xh (16B pieces, coalesced)
        {
            float* a = Af(st);
#pragma unroll
            for (int i = 0; i < 4; i++) {
                int idx = tid + i * 256;
                int row = idx >> 2, c8 = idx & 3;
                float4 v0 = *reinterpret_cast<float4*>(a + row * 36 + c8 * 8);
                float4 v1 = *reinterpret_cast<float4*>(a + row * 36 + c8 * 8 + 4);
                uint4 pack;
                pack.x = h2u(__floats2half2_rn(v0.x, v0.y));
                pack.y = h2u(__floats2half2_rn(v0.z, v0.w));
                pack.z = h2u(__floats2half2_rn(v1.x, v1.y));
                pack.w = h2u(__floats2half2_rn(v1.z, v1.w));
                *reinterpret_cast<uint4*>(hbuf + row * 40 + c8 * 8) = pack;
                *reinterpret_cast<uint4*>(
                    g_xh + (size_t)(m0 + row) * Cdim + kt + c8 * 8) = pack;
            }
        }
        __syncthreads();
#pragma unroll
        for (int kk = 0; kk < 32; kk += 16) {
            HAFragR a[4];
#pragma unroll
            for (int i = 0; i < 4; i++)
                wmma::load_matrix_sync(a[i], hbuf + (wm * 64 + i * 16) * 40 + kk, 40);
#pragma unroll
            for (int j = 0; j < 4; j++) {
                HBFragR bf;
                wmma::load_matrix_sync(bf, Ws(st) + kk * 136 + wn * 64 + j * 16, 136);
#pragma unroll
                for (int i = 0; i < 4; i++) wmma::mma_sync(c[i][j], a[i], bf, c[i][j]);
            }
        }
        __syncthreads();
    }

    // epilogue: tile -> smem fp32 [256][132], write gmem + column stats
#pragma unroll
    for (int i = 0; i < 4; i++)
#pragma unroll
        for (int j = 0; j < 4; j++)
            wmma::store_matrix_sync(shf + (wm * 64 + i * 16) * 132 + wn * 64 + j * 16,
                                    c[i][j], 132, wmma::mem_row_major);
    __syncthreads();
#pragma unroll
    for (int i = 0; i < 32; i++) {
        int idx = tid + i * 256;
        int row = idx >> 5, c4 = idx & 31;
        float4 v = *reinterpret_cast<float4*>(shf + row * 132 + c4 * 4);
        *reinterpret_cast<float4*>(g_logits + (size_t)(m0 + row) * Hdim + c4 * 4) = v;
    }
    {
        float* pm = shf + 33792;
        float* ps = shf + 34048;
        const int col = tid & 127, half = tid >> 7;
        float m = -1e30f;
#pragma unroll 8
        for (int r = half * 128; r < half * 128 + 128; r++)
            m = fmaxf(m, shf[r * 132 + col]);
        float s = 0.0f;
#pragma unroll 8
        for (int r = half * 128; r < half * 128 + 128; r++)
            s += __expf(shf[r * 132 + col] - m);
        pm[tid] = m; ps[tid] = s;
        __syncthreads();
        if (half == 0) {
            float m1 = pm[col + 128], s1 = ps[col + 128];
            float mn = fmaxf(m, m1);
            float sc = s * __expf(m - mn) + s1 * __expf(m1 - mn);
            const int b = blockIdx.x >> 5, ch = blockIdx.x & 31;
            g_part_m[((size_t)b * NCH + ch) * Hdim + col] = mn;
            g_part_s[((size_t)b * NCH + ch) * Hdim + col] = sc;
        }
    }
}

// ============================================================================
// K2: A = fp16_RN(exp(l - m) * inv). Each block combines the 32 chunk stats
// itself (replaces k_comb), then converts 64 s-rows x 128 h.
// grid = 1024 blocks (b = bx>>7, s0 = (bx&127)*64).
// ============================================================================
__global__ __launch_bounds__(256) void k_aconv() {
    __shared__ float sm[128], si[128];
    const int tid = threadIdx.x;
    const int b = blockIdx.x >> 7;
    const int s0 = (blockIdx.x & 127) * 64;

    if (tid < 128) {
        float m = -1e30f, s = 0.0f;
#pragma unroll
        for (int ch = 0; ch < NCH; ch++) {
            float pm = g_part_m[((size_t)b * NCH + ch) * Hdim + tid];
            float ps = g_part_s[((size_t)b * NCH + ch) * Hdim + tid];
            float mn = fmaxf(m, pm);
            s = s * __expf(m - mn) + ps * __expf(pm - mn);
            m = mn;
        }
        sm[tid] = m;
        si[tid] = 1.0f / s;
    }
    __syncthreads();

#pragma unroll
    for (int i = 0; i < 8; i++) {          // 64 rows x 128 h = 2048 f4
        int idx = tid + i * 256;
        int row = idx >> 5, h4 = (idx & 31) * 4;
        size_t g = ((size_t)b * Sdim + s0 + row) * Hdim + h4;
        float4 l = *reinterpret_cast<float4*>(g_logits + g);
        float a0 = __expf(l.x - sm[h4 + 0]) * si[h4 + 0];
        float a1 = __expf(l.y - sm[h4 + 1]) * si[h4 + 1];
        float a2 = __expf(l.z - sm[h4 + 2]) * si[h4 + 2];
        float a3 = __expf(l.w - sm[h4 + 3]) * si[h4 + 3];
        __half2* dst = reinterpret_cast<__half2*>(g_ah + g);
        dst[0] = __floats2half2_rn(a0, a1);
        dst[1] = __floats2half2_rn(a2, a3);
    }
}

// ============================================================================
// K3: ctxT_part[ks][b] = x^T @ A over a 1024-row s-slice. fp16 operands.
// Output ctx^T tile [c=256][h=128]. Warp 64x64, KC=32, 3-stage.
// grid (2 ct, 8 ks, 8 b) = 128 blocks.  (4th launch -> gets profiled)
// ============================================================================
__global__ __launch_bounds__(256, 1) void k_ctx() {
    extern __shared__ char shc[];
    __half* shh = reinterpret_cast<__half*>(shc);
    // stage stride = x 32*264 + A 32*136 = 12800 halves
    const int tid = threadIdx.x, wid = tid >> 5;
    const int wm = wid >> 1, wn = wid & 1;
    const int ct = blockIdx.x, ks = blockIdx.y, b = blockIdx.z;
    const int sbase = ks * SLICE;
    const int c0 = ct * 256;

    HAcc c[4][4];
#pragma unroll
    for (int i = 0; i < 4; i++)
#pragma unroll
        for (int j = 0; j < 4; j++) wmma::fill_fragment(c[i][j], 0.0f);

    auto Xs = [&](int st) { return shh + st * 12800; };           // [32 s][264]
    auto Bs = [&](int st) { return shh + st * 12800 + 8448; };    // [32 s][136]

    auto load_tiles = [&](int st, int it) {
        const int s0 = sbase + it * 32;
        __half* xs = Xs(st);
        __half* bsh = Bs(st);
#pragma unroll
        for (int i = 0; i < 4; i++) {      // x: 32x256 halves = 1024 chunks
            int idx = tid + i * 256;
            int row = idx >> 5, c8 = idx & 31;
            cp16(xs + row * 264 + c8 * 8,
                 g_xh + ((size_t)b * Sdim + s0 + row) * Cdim + c0 + c8 * 8);
        }
#pragma unroll
        for (int i = 0; i < 2; i++) {      // A: 32x128 halves = 512 chunks
            int idx = tid + i * 256;
            int row = idx >> 4, c8 = idx & 15;
            cp16(bsh + row * 136 + c8 * 8,
                 g_ah + ((size_t)b * Sdim + s0 + row) * Hdim + c8 * 8);
        }
    };

    const int NIT = SLICE / 32;   // 32
    load_tiles(0, 0); CP_COMMIT;
    load_tiles(1, 1); CP_COMMIT;
    for (int it = 0; it < NIT; ++it) {
        if (it + 2 < NIT) load_tiles((it + 2) % 3, it + 2);
        CP_COMMIT;
        CP_WAIT2;
        __syncthreads();
        const int st = it % 3;
#pragma unroll
        for (int kk = 0; kk < 32; kk += 16) {
            HAFragC a[4];    // M=c from x[s][c] col-major view
#pragma unroll
            for (int i = 0; i < 4; i++)
                wmma::load_matrix_sync(a[i], Xs(st) + kk * 264 + wm * 64 + i * 16, 264);
#pragma unroll
            for (int j = 0; j < 4; j++) {
                HBFragR bf;
                wmma::load_matrix_sync(bf, Bs(st) + kk * 136 + wn * 64 + j * 16, 136);
#pragma unroll
                for (int i = 0; i < 4; i++) wmma::mma_sync(c[i][j], a[i], bf, c[i][j]);
            }
        }
        __syncthreads();
    }
#pragma unroll
    for (int i = 0; i < 4; i++)
#pragma unroll
        for (int j = 0; j < 4; j++)
            wmma::store_matrix_sync(
                g_ctxT_part + (((size_t)ks * Bdim + b) * Cdim + c0 + wm * 64 + i * 16) * Hdim +
                    wn * 64 + j * 16,
                c[i][j], Hdim, wmma::mem_row_major);
}

// K4: deterministic split-K reduce -> g_cth fp16 [b][c][h]
__global__ __launch_bounds__(256) void k_reduce() {
    const size_t f4 = (size_t)blockIdx.x * 256 + threadIdx.x;  // 131072
    float4 s = make_float4(0.f, 0.f, 0.f, 0.f);
#pragma unroll
    for (int p = 0; p < KSPLIT; p++) {
        float4 v = reinterpret_cast<float4*>(
            g_ctxT_part + (size_t)p * Bdim * Cdim * Hdim)[f4];
        s.x += v.x; s.y += v.y; s.z += v.z; s.w += v.w;
    }
    __half2* dst = reinterpret_cast<__half2*>(g_cth) + f4 * 2;
    dst[0] = __floats2half2_rn(s.x, s.y);
    dst[1] = __floats2half2_rn(s.z, s.w);
}

// ============================================================================
// K5: out = A @ ctx. M=8192(s), N=512(c), K=128(h). fp16 operands.
// B = ctx^T fp16 consumed col-major. Block 256x128, warp 64x64, KC=32.
// grid (4 ct, 32 mt, 8 b), ct fastest.
// ============================================================================
__global__ __launch_bounds__(256, 1) void k_out(float* __restrict__ out) {
    extern __shared__ char shc[];
    __half* shh = reinterpret_cast<__half*>(shc);
    // stage stride = A 256*40 + ctxT 128*40 = 15360 halves
    const int tid = threadIdx.x, wid = tid >> 5;
    const int wm = wid >> 1, wn = wid & 1;
    const int ct = blockIdx.x, mt = blockIdx.y, b = blockIdx.z;
    const int m0 = mt * 256, c0 = ct * 128;

    HAcc c[4][4];
#pragma unroll
    for (int i = 0; i < 4; i++)
#pragma unroll
        for (int j = 0; j < 4; j++) wmma::fill_fragment(c[i][j], 0.0f);

    auto As = [&](int st) { return shh + st * 15360; };           // [256 s][40]
    auto Bs = [&](int st) { return shh + st * 15360 + 10240; };   // [128 c][40]

    auto load_tiles = [&](int st, int it) {
        const int kt = it * 32;
        __half* a = As(st);
        __half* bsh = Bs(st);
#pragma unroll
        for (int i = 0; i < 4; i++) {      // A: 256x32 halves = 1024 chunks
            int idx = tid + i * 256;
            int row = idx >> 2, c8 = idx & 3;
            cp16(a + row * 40 + c8 * 8,
                 g_ah + ((size_t)b * Sdim + m0 + row) * Hdim + kt + c8 * 8);
        }
#pragma unroll
        for (int i = 0; i < 2; i++) {      // ctxT: 128x32 halves = 512 chunks
            int idx = tid + i * 256;
            int row = idx >> 2, c8 = idx & 3;
            cp16(bsh + row * 40 + c8 * 8,
                 g_cth + ((size_t)b * Cdim + c0 + row) * Hdim + kt + c8 * 8);
        }
    };

    const int NIT = 4;
    load_tiles(0, 0); CP_COMMIT;
    load_tiles(1, 1); CP_COMMIT;
    for (int it = 0; it < NIT; ++it) {
        if (it + 2 < NIT) load_tiles((it + 2) % 3, it + 2);
        CP_COMMIT;
        CP_WAIT2;
        __syncthreads();
        const int st = it % 3;
#pragma unroll
        for (int kk = 0; kk < 32; kk += 16) {
            HAFragR a[4];
#pragma unroll
            for (int i = 0; i < 4; i++)
                wmma::load_matrix_sync(a[i], As(st) + (wm * 64 + i * 16) * 40 + kk, 40);
#pragma unroll
            for (int j = 0; j < 4; j++) {
                HBFragC bf;   // B[k=h][n=c] at Bs[c][h] -> col-major, ldm 40
                wmma::load_matrix_sync(bf, Bs(st) + (wn * 64 + j * 16) * 40 + kk, 40);
#pragma unroll
                for (int i = 0; i < 4; i++) wmma::mma_sync(c[i][j], a[i], bf, c[i][j]);
            }
        }
        __syncthreads();
    }
#pragma unroll
    for (int i = 0; i < 4; i++)
#pragma unroll
        for (int j = 0; j < 4; j++)
            wmma::store_matrix_sync(
                out + ((size_t)b * Sdim + m0 + wm * 64 + i * 16) * Cdim + c0 +
                    wn * 64 + j * 16,
                c[i][j], Cdim, wmma::mem_row_major);
}

// ============================================================================
extern "C" void kernel_launch(void* const* d_in, const int* in_sizes, int n_in,
                              void* d_out, int out_size) {
    const float* x = (const float*)d_in[0];  // [B, S, C]
    const float* W = (const float*)d_in[1];  // [C, H]
    // d_in[2] (bias) cancels in softmax over S — skipped, exact.
    float* out = (float*)d_out;

    const size_t sh_logits = 157184;   // fp32 A stages + fp16 W stages + fp16 buf
    const size_t sh_ctx    = 76800;
    const size_t sh_out    = 92160;
    cudaFuncSetAttribute(k_logits, cudaFuncAttributeMaxDynamicSharedMemorySize,
                         (int)sh_logits);
    cudaFuncSetAttribute(k_ctx, cudaFuncAttributeMaxDynamicSharedMemorySize,
                         (int)sh_ctx);
    cudaFuncSetAttribute(k_out, cudaFuncAttributeMaxDynamicSharedMemorySize,
                         (int)sh_out);

    k_wr<<<Cdim * Hdim / 256, 256>>>(W);
    k_logits<<<(Bdim * Sdim) / 256, 256, sh_logits>>>(x);
    k_aconv<<<1024, 256>>>();
    k_ctx<<<dim3(Cdim / 256, KSPLIT, Bdim), 256, sh_ctx>>>();   // 4th launch
    k_reduce<<<512, 256>>>();
    k_out<<<dim3(Cdim / 128, Sdim / 256, Bdim), 256, sh_out>>>(out);
}